// round 9
// baseline (speedup 1.0000x reference)
#include <cuda_runtime.h>
#include <math.h>

#define HID 128
#define NOP 50000
#define NMA 1000
#define NJOB 5000
#define NALL 56000
#define NLAYERS 3
#define EMAX 150000
#define FULLMASK 0xffffffffu

// ---------------- device scratch ----------------
__device__ float g_x[NALL * HID];
__device__ float g_agg[NALL * HID];
__device__ float g_xs3[NOP * 384];        // merged src proj for relations 0,1,4
__device__ float g_xsm[NMA * HID];        // src proj relation 2
__device__ float g_xsj[NJOB * HID];       // src proj relation 3
__device__ float g_asL[5 * NOP * 8];      // per-relation src dots
__device__ float g_adL[5 * NOP * 8];      // per-relation dst dots
__device__ float g_aes[5 * EMAX * 8];     // per-relation edge dots (CSR order)
__device__ float g_ws[15 * HID * 8];
__device__ float g_wd[15 * HID * 8];
__device__ float g_Me[15 * 32 * 8];
__device__ float g_ce[15 * 8];
__device__ float g_Wcat[3 * HID * 384];
// CSR
__device__ int g_rowptr[5 * (NOP + 1)];
__device__ int g_srcs[5 * EMAX];
__device__ int g_epos[5 * EMAX];
__device__ int g_cnt[NOP];
__device__ int g_cursor[NOP];
// BN
__device__ double g_part[2 * 3 * 64 * HID];
__device__ float g_scale[3 * HID];
__device__ float g_shift[3 * HID];

struct DotArgs { const float* w[6]; float* out[6]; int nw; int H; };
struct EAArgs  { const float* ea[5]; };
struct GArgs   { const float* xs[5]; int rs[5]; const float* bg; };

// ---------------- fold kernel ----------------
__global__ void fold_kernel(const float* __restrict__ Wg, const float* __restrict__ att_s,
                            const float* __restrict__ att_d, const float* __restrict__ Wge,
                            const float* __restrict__ att_e, const float* __restrict__ We_proj,
                            const float* __restrict__ be_proj) {
    int slot = blockIdx.x;
    int i = slot / 5, t = slot % 5;
    int H = (i < NLAYERS - 1) ? 8 : 1;
    int C = HID / H;
    int k = threadIdx.x;
    const float* Wg_  = Wg  + (size_t)slot * HID * HID;
    const float* Wge_ = Wge + (size_t)slot * HID * HID;
    const float* as_  = att_s + slot * HID;
    const float* ad_  = att_d + slot * HID;
    const float* ae_  = att_e + slot * HID;

    float ws[8] = {0,0,0,0,0,0,0,0};
    float wd[8] = {0,0,0,0,0,0,0,0};
    float we[8] = {0,0,0,0,0,0,0,0};
    for (int j = 0; j < HID; j++) {
        int h = j / C;
        float w1 = Wg_[k * HID + j];
        ws[h] += w1 * as_[j];
        wd[h] += w1 * ad_[j];
        float w2 = Wge_[k * HID + j];
        we[h] += w2 * ae_[j];
    }
    #pragma unroll
    for (int h = 0; h < 8; h++) {
        g_ws[slot * HID * 8 + k * 8 + h] = ws[h];
        g_wd[slot * HID * 8 + k * 8 + h] = wd[h];
    }
    __shared__ float wef[HID * 8];
    #pragma unroll
    for (int h = 0; h < 8; h++) wef[k * 8 + h] = we[h];
    __syncthreads();

    if (k < 32) {
        const float* Wep = We_proj + (size_t)t * 32 * HID + (size_t)k * HID;
        float me[8] = {0,0,0,0,0,0,0,0};
        for (int j = 0; j < HID; j++) {
            float v = Wep[j];
            #pragma unroll
            for (int h = 0; h < 8; h++) me[h] += v * wef[j * 8 + h];
        }
        #pragma unroll
        for (int h = 0; h < 8; h++) g_Me[slot * 32 * 8 + k * 8 + h] = me[h];
    }
    if (k == 32) {
        const float* bep = be_proj + t * HID;
        float ce[8] = {0,0,0,0,0,0,0,0};
        for (int j = 0; j < HID; j++) {
            float v = bep[j];
            #pragma unroll
            for (int h = 0; h < 8; h++) ce[h] += v * wef[j * 8 + h];
        }
        #pragma unroll
        for (int h = 0; h < 8; h++) g_ce[slot * 8 + h] = ce[h];
    }
}

// ---------------- pack Wcat ----------------
__global__ void pack_wcat(const float* __restrict__ Wg) {
    int idx = blockIdx.x * blockDim.x + threadIdx.x;
    if (idx >= 3 * HID * 384) return;
    int i = idx / (HID * 384);
    int rem = idx % (HID * 384);
    int k = rem / 384, c = rem % 384;
    int r = c / 128, j = c % 128;
    const int tsel[3] = {0, 1, 4};
    g_Wcat[idx] = Wg[(((size_t)(i * 5 + tsel[r])) * HID + k) * HID + j];
}

// ---------------- double-buffered SGEMM ----------------
__global__ __launch_bounds__(256, 2) void gemm3(const float* __restrict__ A,
                                                const float* __restrict__ B,
                                                const float* __restrict__ bias,
                                                float* __restrict__ C,
                                                int M, int K, int N) {
    __shared__ float As[2][16][132];
    __shared__ float Bs[2][16][128];
    int tid = threadIdx.x;
    int tx = tid & 15, ty = tid >> 4;
    int row0 = blockIdx.x * 128, col0 = blockIdx.y * 128;
    int ar0 = tid >> 2, ak0 = (tid & 3) * 4;
    int bk0 = tid >> 5, bc0 = (tid & 31) * 4;
    float4 pa[2], pb[2];

    #define FETCH(kk)                                                             \
        _Pragma("unroll")                                                         \
        for (int i = 0; i < 2; i++) {                                             \
            int gr = row0 + ar0 + i * 64;                                         \
            pa[i] = make_float4(0.f, 0.f, 0.f, 0.f);                              \
            if (gr < M) pa[i] = *(const float4*)(A + (size_t)gr * K + (kk) + ak0);\
            pb[i] = *(const float4*)(B + (size_t)((kk) + bk0 + i * 8) * N + col0 + bc0); \
        }
    #define STORE(buf)                                                            \
        _Pragma("unroll")                                                         \
        for (int i = 0; i < 2; i++) {                                             \
            int ar = ar0 + i * 64;                                                \
            As[buf][ak0 + 0][ar] = pa[i].x;  As[buf][ak0 + 1][ar] = pa[i].y;      \
            As[buf][ak0 + 2][ar] = pa[i].z;  As[buf][ak0 + 3][ar] = pa[i].w;      \
            *(float4*)&Bs[buf][bk0 + i * 8][bc0] = pb[i];                         \
        }

    FETCH(0); STORE(0); __syncthreads();

    float acc[8][8];
    #pragma unroll
    for (int r = 0; r < 8; r++)
        #pragma unroll
        for (int c = 0; c < 8; c++) acc[r][c] = 0.f;

    int nt = K >> 4;
    for (int t = 0; t < nt; t++) {
        int buf = t & 1;
        if (t + 1 < nt) { FETCH((t + 1) << 4); }
        #pragma unroll
        for (int k = 0; k < 16; k++) {
            float a[8], b[8];
            *(float4*)&a[0] = *(const float4*)&As[buf][k][ty * 4];
            *(float4*)&a[4] = *(const float4*)&As[buf][k][64 + ty * 4];
            *(float4*)&b[0] = *(const float4*)&Bs[buf][k][tx * 4];
            *(float4*)&b[4] = *(const float4*)&Bs[buf][k][64 + tx * 4];
            #pragma unroll
            for (int r = 0; r < 8; r++)
                #pragma unroll
                for (int c = 0; c < 8; c++) acc[r][c] += a[r] * b[c];
        }
        if (t + 1 < nt) { STORE(buf ^ 1); }
        __syncthreads();
    }
    #pragma unroll
    for (int ri = 0; ri < 2; ri++) {
        #pragma unroll
        for (int r = 0; r < 4; r++) {
            int gr = row0 + ri * 64 + ty * 4 + r;
            if (gr >= M) continue;
            #pragma unroll
            for (int ci = 0; ci < 2; ci++) {
                int gc = col0 + ci * 64 + tx * 4;
                float4 v;
                v.x = acc[ri * 4 + r][ci * 4 + 0];
                v.y = acc[ri * 4 + r][ci * 4 + 1];
                v.z = acc[ri * 4 + r][ci * 4 + 2];
                v.w = acc[ri * 4 + r][ci * 4 + 3];
                if (bias) {
                    v.x += bias[gc + 0]; v.y += bias[gc + 1];
                    v.z += bias[gc + 2]; v.w += bias[gc + 3];
                }
                *(float4*)(C + (size_t)gr * N + gc) = v;
            }
        }
    }
    #undef FETCH
    #undef STORE
}

// ---------------- fused attention dots ----------------
__global__ void dots_kernel(const float* __restrict__ x, int n, DotArgs da) {
    __shared__ float sw[6 * 1024];
    int tid = threadIdx.x;
    int tot = da.nw * 1024;
    for (int i = tid; i < tot; i += 256) sw[i] = da.w[i >> 10][i & 1023];
    __syncthreads();
    int node = blockIdx.x * 8 + (tid >> 5);
    int lane = tid & 31;
    if (node >= n) return;
    float xv[4];
    #pragma unroll
    for (int i = 0; i < 4; i++) xv[i] = x[(size_t)node * HID + lane + 32 * i];
    for (int j = 0; j < da.nw; j++) {
        float acc[8] = {0,0,0,0,0,0,0,0};
        #pragma unroll
        for (int i = 0; i < 4; i++) {
            const float* wp = &sw[j * 1024 + (lane + 32 * i) * 8];
            #pragma unroll
            for (int h = 0; h < 8; h++) acc[h] += xv[i] * wp[h];
        }
        #pragma unroll
        for (int off = 16; off > 0; off >>= 1)
            #pragma unroll
            for (int h = 0; h < 8; h++) acc[h] += __shfl_xor_sync(FULLMASK, acc[h], off);
        if (lane == 0)
            for (int h = 0; h < da.H; h++) da.out[j][(size_t)node * da.H + h] = acc[h];
    }
}

// ---------------- batched edge attention dots ----------------
__global__ void edge_ae_all(EAArgs ea, const float* __restrict__ Me_base,
                            const float* __restrict__ ce_base, int H) {
    const int Esz[5] = {150000, 100000, 150000, 100000, 100000};
    int t = blockIdx.y;
    int E = Esz[t];
    __shared__ float sMe[256];
    __shared__ float sce[8];
    int tid = threadIdx.x;
    sMe[tid] = Me_base[t * 256 + tid];
    if (tid < 8) sce[tid] = ce_base[t * 8 + tid];
    __syncthreads();
    int e = blockIdx.x * 256 + tid;
    if (e >= E) return;
    const float* er = ea.ea[t] + (size_t)e * 32;
    float acc[8];
    #pragma unroll
    for (int h = 0; h < 8; h++) acc[h] = sce[h];
    #pragma unroll 8
    for (int k = 0; k < 32; k++) {
        float v = er[k];
        #pragma unroll
        for (int h = 0; h < 8; h++) acc[h] += v * sMe[k * 8 + h];
    }
    int pos = g_epos[t * EMAX + e];
    float* out = g_aes + (size_t)t * EMAX * 8;
    for (int h = 0; h < H; h++) out[(size_t)pos * H + h] = acc[h];
}

// ---------------- CSR build ----------------
__global__ void zero_int_kernel(int* p, int n) {
    int i = blockIdx.x * blockDim.x + threadIdx.x;
    if (i < n) p[i] = 0;
}
__global__ void hist_kernel(const int* __restrict__ EI, int E, int* __restrict__ cnt) {
    int e = blockIdx.x * blockDim.x + threadIdx.x;
    if (e < E) atomicAdd(&cnt[EI[E + e]], 1);
}
__global__ void scan_kernel(const int* __restrict__ cnt, int* __restrict__ rowptr, int n) {
    __shared__ int sh[1024];
    __shared__ int base;
    int tid = threadIdx.x;
    if (tid == 0) base = 0;
    __syncthreads();
    for (int i0 = 0; i0 < n; i0 += 1024) {
        int i = i0 + tid;
        int v = (i < n) ? cnt[i] : 0;
        sh[tid] = v;
        __syncthreads();
        for (int off = 1; off < 1024; off <<= 1) {
            int t = (tid >= off) ? sh[tid - off] : 0;
            __syncthreads();
            sh[tid] += t;
            __syncthreads();
        }
        if (i < n) rowptr[i] = base + sh[tid] - v;
        __syncthreads();
        if (tid == 1023) base += sh[1023];
        __syncthreads();
    }
    if (tid == 0) rowptr[n] = base;
}
__global__ void scatter_kernel(const int* __restrict__ EI, int E,
                               const int* __restrict__ rowptr, int* __restrict__ cursor,
                               int* __restrict__ srcs, int* __restrict__ epos) {
    int e = blockIdx.x * blockDim.x + threadIdx.x;
    if (e >= E) return;
    int dst = EI[E + e];
    int pos = rowptr[dst] + atomicAdd(&cursor[dst], 1);
    srcs[pos] = EI[e];
    epos[e] = pos;
}

// ---------------- merged gather: two-pass softmax, templated on H ----------------
template <int H>
__global__ void gat_gather_all(GArgs ga) {
    int w = (blockIdx.x * blockDim.x + threadIdx.x) >> 5;
    int lane = threadIdx.x & 31;
    if (w >= NALL) return;
    const int hl = (lane * 4 * H) >> 7;  // head owning this lane's 4 cols
    int nrel, rels[3], node;
    float4 tot;
    const float* bgp = ga.bg;
    if (w < NOP) {
        node = w; nrel = 3; rels[0] = 0; rels[1] = 2; rels[2] = 3;
        float4 b0 = *(const float4*)(bgp + 0 * HID + lane * 4);
        float4 b2 = *(const float4*)(bgp + 2 * HID + lane * 4);
        float4 b3 = *(const float4*)(bgp + 3 * HID + lane * 4);
        tot = make_float4(b0.x + b2.x + b3.x, b0.y + b2.y + b3.y,
                          b0.z + b2.z + b3.z, b0.w + b2.w + b3.w);
    } else if (w < NOP + NMA) {
        node = w - NOP; nrel = 1; rels[0] = 1;
        tot = *(const float4*)(bgp + 1 * HID + lane * 4);
    } else {
        node = w - NOP - NMA; nrel = 1; rels[0] = 4;
        tot = *(const float4*)(bgp + 4 * HID + lane * 4);
    }
    for (int ri = 0; ri < nrel; ri++) {
        int r = rels[ri];
        const int* rp = g_rowptr + r * (NOP + 1);
        int beg = rp[node], end = rp[node + 1];
        const int* sr = g_srcs + r * EMAX;
        const float* aes = g_aes + (size_t)r * EMAX * 8;
        const float* asb = g_asL + (size_t)r * NOP * 8;
        float adv = (lane < H) ? g_adL[(size_t)r * NOP * 8 + (size_t)node * H + lane] : 0.f;
        const float* xs = ga.xs[r];
        int rs = ga.rs[r];
        // pass A: per-head segment max (no xs traffic, no shfl, no branch dep)
        float m = -1e30f;
        #pragma unroll 4
        for (int p = beg; p < end; p++) {
            if (lane < H) {
                int s = sr[p];
                float lg = asb[(size_t)s * H + lane] + adv + aes[(size_t)p * H + lane];
                lg = lg > 0.f ? lg : 0.2f * lg;
                m = fmaxf(m, lg);
            }
        }
        // pass B: exp + accumulate (no serial dependency except FMA chains)
        float den = 0.f;
        float4 acc = make_float4(0.f, 0.f, 0.f, 0.f);
        #pragma unroll 2
        for (int p = beg; p < end; p++) {
            int s = sr[p];
            float ex = 0.f;
            if (lane < H) {
                float lg = asb[(size_t)s * H + lane] + adv + aes[(size_t)p * H + lane];
                lg = lg > 0.f ? lg : 0.2f * lg;
                ex = __expf(lg - m);
                den += ex;
            }
            float wv = (H == 1) ? __shfl_sync(FULLMASK, ex, 0)
                                : __shfl_sync(FULLMASK, ex, hl);
            const float4 xv = *(const float4*)(xs + (size_t)s * rs + lane * 4);
            acc.x += wv * xv.x; acc.y += wv * xv.y;
            acc.z += wv * xv.z; acc.w += wv * xv.w;
        }
        float dhl = (H == 1) ? __shfl_sync(FULLMASK, den, 0)
                             : __shfl_sync(FULLMASK, den, hl);
        float inv = 1.f / (dhl + 1e-16f);
        tot.x += acc.x * inv; tot.y += acc.y * inv;
        tot.z += acc.z * inv; tot.w += acc.w * inv;
    }
    *(float4*)(g_agg + (size_t)w * HID + lane * 4) = tot;
}

// ---------------- BN ----------------
__global__ void bn_stats_kernel() {
    const int offs[3] = {0, NOP, NOP + NMA};
    const int cnts[3] = {NOP, NMA, NJOB};
    int type = blockIdx.y;
    int col = threadIdx.x;
    int N = cnts[type], off = offs[type];
    double s = 0.0, s2 = 0.0;
    for (int r = blockIdx.x; r < N; r += 64) {
        float v = g_agg[(size_t)(off + r) * HID + col];
        s += (double)v;
        s2 += (double)v * (double)v;
    }
    g_part[((0 * 3 + type) * 64 + blockIdx.x) * HID + col] = s;
    g_part[((1 * 3 + type) * 64 + blockIdx.x) * HID + col] = s2;
}

__global__ void bn_finalize_kernel(const float* __restrict__ gamma,
                                   const float* __restrict__ beta, int layer) {
    const int cnts[3] = {NOP, NMA, NJOB};
    int idx = threadIdx.x + blockIdx.x * blockDim.x;
    if (idx >= 3 * HID) return;
    int type = idx / HID, col = idx % HID;
    double s = 0.0, s2 = 0.0;
    for (int c = 0; c < 64; c++) {
        s  += g_part[((0 * 3 + type) * 64 + c) * HID + col];
        s2 += g_part[((1 * 3 + type) * 64 + c) * HID + col];
    }
    double N = (double)cnts[type];
    double mu = s / N;
    double var = s2 / N - mu * mu;
    if (var < 0.0) var = 0.0;
    float g = gamma[layer * 3 * HID + type * HID + col];
    float b = beta[layer * 3 * HID + type * HID + col];
    float sc = g * rsqrtf((float)var + 1e-5f);
    g_scale[idx] = sc;
    g_shift[idx] = b - (float)mu * sc;
}

__global__ void bn_apply_kernel(int layer) {
    int idx = blockIdx.x * blockDim.x + threadIdx.x;
    if (idx >= NALL * HID) return;
    int row = idx / HID, col = idx % HID;
    int type = (row < NOP) ? 0 : ((row < NOP + NMA) ? 1 : 2);
    float v = g_agg[idx] * g_scale[type * HID + col] + g_shift[type * HID + col];
    if (layer < NLAYERS - 1) v = fmaxf(v, 0.f);
    g_x[idx] = g_x[idx] + v;
}

// ---------------- launch ----------------
extern "C" void kernel_launch(void* const* d_in, const int* in_sizes, int n_in,
                              void* d_out, int out_size) {
    const float* x_op  = (const float*)d_in[0];
    const float* x_ma  = (const float*)d_in[1];
    const float* x_job = (const float*)d_in[2];

    const int* EI[5];
    const float* EA[5];
    bool interleaved = (in_sizes[4] > 1000000);
    if (interleaved) {
        for (int t = 0; t < 5; t++) {
            EI[t] = (const int*)d_in[3 + 2 * t];
            EA[t] = (const float*)d_in[4 + 2 * t];
        }
    } else {
        for (int t = 0; t < 5; t++) {
            EI[t] = (const int*)d_in[3 + t];
            EA[t] = (const float*)d_in[8 + t];
        }
    }

    const float* Wn_op = (const float*)d_in[13];
    const float* bn_op = (const float*)d_in[14];
    const float* Wn_ma = (const float*)d_in[15];
    const float* bn_ma = (const float*)d_in[16];
    const float* Wn_job = (const float*)d_in[17];
    const float* bn_job = (const float*)d_in[18];
    const float* We_proj = (const float*)d_in[19];
    const float* be_proj = (const float*)d_in[20];
    const float* Wg    = (const float*)d_in[21];
    const float* att_s = (const float*)d_in[22];
    const float* att_d = (const float*)d_in[23];
    const float* Wge   = (const float*)d_in[24];
    const float* att_e = (const float*)d_in[25];
    const float* bg    = (const float*)d_in[26];
    const float* gamma = (const float*)d_in[27];
    const float* beta  = (const float*)d_in[28];
    const float* Wo    = (const float*)d_in[29];
    const float* bo    = (const float*)d_in[30];

    static const int Esz[5]  = {150000, 100000, 150000, 100000, 100000};
    static const int Tdst[5] = {0, 1, 0, 0, 2};
    static const int cntn[3] = {NOP, NMA, NJOB};

    float* gx;    cudaGetSymbolAddress((void**)&gx, g_x);
    float* gxs3;  cudaGetSymbolAddress((void**)&gxs3, g_xs3);
    float* gxsm;  cudaGetSymbolAddress((void**)&gxsm, g_xsm);
    float* gxsj;  cudaGetSymbolAddress((void**)&gxsj, g_xsj);
    float* gasL;  cudaGetSymbolAddress((void**)&gasL, g_asL);
    float* gadL;  cudaGetSymbolAddress((void**)&gadL, g_adL);
    float* gws;   cudaGetSymbolAddress((void**)&gws, g_ws);
    float* gwd;   cudaGetSymbolAddress((void**)&gwd, g_wd);
    float* gMe;   cudaGetSymbolAddress((void**)&gMe, g_Me);
    float* gce;   cudaGetSymbolAddress((void**)&gce, g_ce);
    float* gWcat; cudaGetSymbolAddress((void**)&gWcat, g_Wcat);
    int* grp;     cudaGetSymbolAddress((void**)&grp, g_rowptr);
    int* gsrc;    cudaGetSymbolAddress((void**)&gsrc, g_srcs);
    int* gep;     cudaGetSymbolAddress((void**)&gep, g_epos);
    int* gcnt;    cudaGetSymbolAddress((void**)&gcnt, g_cnt);
    int* gcur;    cudaGetSymbolAddress((void**)&gcur, g_cursor);

    // ---- launches 0-5: ordered so the MERGED LAYER-0 GEMM is launch #5 (ncu -s 5 -c 1) ----
    fold_kernel<<<15, 128>>>(Wg, att_s, att_d, Wge, att_e, We_proj, be_proj);      // 0
    pack_wcat<<<(3 * HID * 384 + 255) / 256, 256>>>(Wg);                           // 1
    gemm3<<<dim3((NOP + 127) / 128, 1), 256>>>(x_op, Wn_op, bn_op, gx, NOP, 64, 128);  // 2
    gemm3<<<dim3((NMA + 127) / 128, 1), 256>>>(x_ma, Wn_ma, bn_ma, gx + (size_t)NOP * HID, NMA, 32, 128);  // 3
    gemm3<<<dim3((NJOB + 127) / 128, 1), 256>>>(x_job, Wn_job, bn_job, gx + (size_t)(NOP + NMA) * HID, NJOB, 16, 128);  // 4
    gemm3<<<dim3((NOP + 127) / 128, 3), 256>>>(gx, gWcat, nullptr, gxs3, NOP, 128, 384);  // 5 <- PROFILED

    // ---- CSR build ----
    for (int t = 0; t < 5; t++) {
        int E = Esz[t];
        int ndst = cntn[Tdst[t]];
        zero_int_kernel<<<(ndst + 255) / 256, 256>>>(gcnt, ndst);
        hist_kernel<<<(E + 255) / 256, 256>>>(EI[t], E, gcnt);
        scan_kernel<<<1, 1024>>>(gcnt, grp + t * (NOP + 1), ndst);
        zero_int_kernel<<<(ndst + 255) / 256, 256>>>(gcur, ndst);
        scatter_kernel<<<(E + 255) / 256, 256>>>(EI[t], E, grp + t * (NOP + 1), gcur,
                                                 gsrc + t * EMAX, gep + t * EMAX);
    }

    EAArgs eaa;
    for (int t = 0; t < 5; t++) eaa.ea[t] = EA[t];

    // ---- layers ----
    for (int i = 0; i < NLAYERS; i++) {
        int H = (i < NLAYERS - 1) ? 8 : 1;
        int b = i * 5;
        // src projections (layer 0's merged one was already launched above)
        if (i > 0)
            gemm3<<<dim3((NOP + 127) / 128, 3), 256>>>(gx, gWcat + (size_t)i * HID * 384,
                                                       nullptr, gxs3, NOP, 128, 384);
        gemm3<<<dim3((NMA + 127) / 128, 1), 256>>>(gx + (size_t)NOP * HID,
                                                   Wg + (size_t)(b + 2) * HID * HID,
                                                   nullptr, gxsm, NMA, 128, 128);
        gemm3<<<dim3((NJOB + 127) / 128, 1), 256>>>(gx + (size_t)(NOP + NMA) * HID,
                                                    Wg + (size_t)(b + 3) * HID * HID,
                                                    nullptr, gxsj, NJOB, 128, 128);
        // fused attention dots per node type
        {
            DotArgs da;
            da.w[0] = gws + (b + 0) * 1024; da.out[0] = gasL + (size_t)0 * NOP * 8;
            da.w[1] = gws + (b + 1) * 1024; da.out[1] = gasL + (size_t)1 * NOP * 8;
            da.w[2] = gws + (b + 4) * 1024; da.out[2] = gasL + (size_t)4 * NOP * 8;
            da.w[3] = gwd + (b + 0) * 1024; da.out[3] = gadL + (size_t)0 * NOP * 8;
            da.w[4] = gwd + (b + 2) * 1024; da.out[4] = gadL + (size_t)2 * NOP * 8;
            da.w[5] = gwd + (b + 3) * 1024; da.out[5] = gadL + (size_t)3 * NOP * 8;
            da.nw = 6; da.H = H;
            dots_kernel<<<(NOP + 7) / 8, 256>>>(gx, NOP, da);
        }
        {
            DotArgs da;
            da.w[0] = gws + (b + 2) * 1024; da.out[0] = gasL + (size_t)2 * NOP * 8;
            da.w[1] = gwd + (b + 1) * 1024; da.out[1] = gadL + (size_t)1 * NOP * 8;
            da.nw = 2; da.H = H;
            dots_kernel<<<(NMA + 7) / 8, 256>>>(gx + (size_t)NOP * HID, NMA, da);
        }
        {
            DotArgs da;
            da.w[0] = gws + (b + 3) * 1024; da.out[0] = gasL + (size_t)3 * NOP * 8;
            da.w[1] = gwd + (b + 4) * 1024; da.out[1] = gadL + (size_t)4 * NOP * 8;
            da.nw = 2; da.H = H;
            dots_kernel<<<(NJOB + 7) / 8, 256>>>(gx + (size_t)(NOP + NMA) * HID, NJOB, da);
        }
        edge_ae_all<<<dim3((EMAX + 255) / 256, 5), 256>>>(eaa, gMe + b * 256, gce + b * 8, H);
        {
            GArgs ga;
            ga.xs[0] = gxs3;        ga.rs[0] = 384;
            ga.xs[1] = gxs3 + 128;  ga.rs[1] = 384;
            ga.xs[2] = gxsm;        ga.rs[2] = 128;
            ga.xs[3] = gxsj;        ga.rs[3] = 128;
            ga.xs[4] = gxs3 + 256;  ga.rs[4] = 384;
            ga.bg = bg + i * 5 * HID;
            if (H == 8)
                gat_gather_all<8><<<(NALL * 32 + 255) / 256, 256>>>(ga);
            else
                gat_gather_all<1><<<(NALL * 32 + 255) / 256, 256>>>(ga);
        }
        bn_stats_kernel<<<dim3(64, 3), 128>>>();
        bn_finalize_kernel<<<2, 256>>>(gamma, beta, i);
        bn_apply_kernel<<<(NALL * HID + 255) / 256, 256>>>(i);
    }

    // ---- output projection ----
    gemm3<<<dim3((NOP + 127) / 128, 1), 256>>>(gx, Wo, bo, (float*)d_out, NOP, 128, 128);
}

// round 10
// speedup vs baseline: 1.1497x; 1.1497x over previous
#include <cuda_runtime.h>
#include <cuda_bf16.h>
#include <math.h>

#define HID 128
#define NOP 50000
#define NMA 1000
#define NJOB 5000
#define NALL 56000
#define NLAYERS 3
#define EMAX 150000
#define FULLMASK 0xffffffffu

// ---------------- device scratch ----------------
__device__ float g_x[NALL * HID];
__device__ float g_agg[NALL * HID];
__device__ float g_xs3[NOP * 384];
__device__ float g_xsm[NMA * HID];
__device__ float g_xsj[NJOB * HID];
__device__ float g_asL[5 * NOP * 8];
__device__ float g_adL[5 * NOP * 8];
__device__ float g_aes[5 * EMAX * 8];
__device__ float g_ws[15 * HID * 8];
__device__ float g_wd[15 * HID * 8];
__device__ float g_Me[15 * 32 * 8];
__device__ float g_ce[15 * 8];
__device__ float g_Wcat[3 * HID * 384];
// bf16 split operands
__device__ __nv_bfloat16 g_xh[NALL * HID];
__device__ __nv_bfloat16 g_xl[NALL * HID];
__device__ __nv_bfloat16 g_WcatH[3 * HID * 384];
__device__ __nv_bfloat16 g_WcatL[3 * HID * 384];
__device__ __nv_bfloat16 g_WsmH[3 * HID * HID];
__device__ __nv_bfloat16 g_WsmL[3 * HID * HID];
__device__ __nv_bfloat16 g_WsjH[3 * HID * HID];
__device__ __nv_bfloat16 g_WsjL[3 * HID * HID];
__device__ __nv_bfloat16 g_WoH[HID * HID];
__device__ __nv_bfloat16 g_WoL[HID * HID];
// CSR
__device__ int g_rowptr[5 * (NOP + 1)];
__device__ int g_srcs[5 * EMAX];
__device__ int g_epos[5 * EMAX];
__device__ int g_cnt[NOP];
__device__ int g_cursor[NOP];
// BN
__device__ double g_part[2 * 3 * 64 * HID];
__device__ float g_scale[3 * HID];
__device__ float g_shift[3 * HID];

struct DotArgs { const float* w[6]; float* out[6]; int nw; int H; };
struct EAArgs  { const float* ea[5]; };
struct GArgs   { const float* xs[5]; int rs[5]; const float* bg; };

// ---------------- fold kernel ----------------
__global__ void fold_kernel(const float* __restrict__ Wg, const float* __restrict__ att_s,
                            const float* __restrict__ att_d, const float* __restrict__ Wge,
                            const float* __restrict__ att_e, const float* __restrict__ We_proj,
                            const float* __restrict__ be_proj) {
    int slot = blockIdx.x;
    int i = slot / 5, t = slot % 5;
    int H = (i < NLAYERS - 1) ? 8 : 1;
    int C = HID / H;
    int k = threadIdx.x;
    const float* Wg_  = Wg  + (size_t)slot * HID * HID;
    const float* Wge_ = Wge + (size_t)slot * HID * HID;
    const float* as_  = att_s + slot * HID;
    const float* ad_  = att_d + slot * HID;
    const float* ae_  = att_e + slot * HID;

    float ws[8] = {0,0,0,0,0,0,0,0};
    float wd[8] = {0,0,0,0,0,0,0,0};
    float we[8] = {0,0,0,0,0,0,0,0};
    for (int j = 0; j < HID; j++) {
        int h = j / C;
        float w1 = Wg_[k * HID + j];
        ws[h] += w1 * as_[j];
        wd[h] += w1 * ad_[j];
        float w2 = Wge_[k * HID + j];
        we[h] += w2 * ae_[j];
    }
    #pragma unroll
    for (int h = 0; h < 8; h++) {
        g_ws[slot * HID * 8 + k * 8 + h] = ws[h];
        g_wd[slot * HID * 8 + k * 8 + h] = wd[h];
    }
    __shared__ float wef[HID * 8];
    #pragma unroll
    for (int h = 0; h < 8; h++) wef[k * 8 + h] = we[h];
    __syncthreads();

    if (k < 32) {
        const float* Wep = We_proj + (size_t)t * 32 * HID + (size_t)k * HID;
        float me[8] = {0,0,0,0,0,0,0,0};
        for (int j = 0; j < HID; j++) {
            float v = Wep[j];
            #pragma unroll
            for (int h = 0; h < 8; h++) me[h] += v * wef[j * 8 + h];
        }
        #pragma unroll
        for (int h = 0; h < 8; h++) g_Me[slot * 32 * 8 + k * 8 + h] = me[h];
    }
    if (k == 32) {
        const float* bep = be_proj + t * HID;
        float ce[8] = {0,0,0,0,0,0,0,0};
        for (int j = 0; j < HID; j++) {
            float v = bep[j];
            #pragma unroll
            for (int h = 0; h < 8; h++) ce[h] += v * wef[j * 8 + h];
        }
        #pragma unroll
        for (int h = 0; h < 8; h++) g_ce[slot * 8 + h] = ce[h];
    }
}

// ---------------- pack Wcat ----------------
__global__ void pack_wcat(const float* __restrict__ Wg) {
    int idx = blockIdx.x * blockDim.x + threadIdx.x;
    if (idx >= 3 * HID * 384) return;
    int i = idx / (HID * 384);
    int rem = idx % (HID * 384);
    int k = rem / 384, c = rem % 384;
    int r = c / 128, j = c % 128;
    const int tsel[3] = {0, 1, 4};
    g_Wcat[idx] = Wg[(((size_t)(i * 5 + tsel[r])) * HID + k) * HID + j];
}

// ---------------- split fp32 -> bf16 hi/lo ----------------
__global__ void cvt_split(const float* __restrict__ src, __nv_bfloat16* __restrict__ h,
                          __nv_bfloat16* __restrict__ l, int n) {
    int i = blockIdx.x * blockDim.x + threadIdx.x;
    if (i >= n) return;
    float v = src[i];
    __nv_bfloat16 hi = __float2bfloat16(v);
    h[i] = hi;
    l[i] = __float2bfloat16(v - __bfloat162float(hi));
}

// ---------------- fp32 SGEMM (kept for small-K input projections) ----------------
__global__ __launch_bounds__(256, 2) void gemm3(const float* __restrict__ A,
                                                const float* __restrict__ B,
                                                const float* __restrict__ bias,
                                                float* __restrict__ C,
                                                int M, int K, int N) {
    __shared__ float As[2][16][132];
    __shared__ float Bs[2][16][128];
    int tid = threadIdx.x;
    int tx = tid & 15, ty = tid >> 4;
    int row0 = blockIdx.x * 128, col0 = blockIdx.y * 128;
    int ar0 = tid >> 2, ak0 = (tid & 3) * 4;
    int bk0 = tid >> 5, bc0 = (tid & 31) * 4;
    float4 pa[2], pb[2];

    #define FETCH(kk)                                                             \
        _Pragma("unroll")                                                         \
        for (int i = 0; i < 2; i++) {                                             \
            int gr = row0 + ar0 + i * 64;                                         \
            pa[i] = make_float4(0.f, 0.f, 0.f, 0.f);                              \
            if (gr < M) pa[i] = *(const float4*)(A + (size_t)gr * K + (kk) + ak0);\
            pb[i] = *(const float4*)(B + (size_t)((kk) + bk0 + i * 8) * N + col0 + bc0); \
        }
    #define STORE(buf)                                                            \
        _Pragma("unroll")                                                         \
        for (int i = 0; i < 2; i++) {                                             \
            int ar = ar0 + i * 64;                                                \
            As[buf][ak0 + 0][ar] = pa[i].x;  As[buf][ak0 + 1][ar] = pa[i].y;      \
            As[buf][ak0 + 2][ar] = pa[i].z;  As[buf][ak0 + 3][ar] = pa[i].w;      \
            *(float4*)&Bs[buf][bk0 + i * 8][bc0] = pb[i];                         \
        }

    FETCH(0); STORE(0); __syncthreads();

    float acc[8][8];
    #pragma unroll
    for (int r = 0; r < 8; r++)
        #pragma unroll
        for (int c = 0; c < 8; c++) acc[r][c] = 0.f;

    int nt = K >> 4;
    for (int t = 0; t < nt; t++) {
        int buf = t & 1;
        if (t + 1 < nt) { FETCH((t + 1) << 4); }
        #pragma unroll
        for (int k = 0; k < 16; k++) {
            float a[8], b[8];
            *(float4*)&a[0] = *(const float4*)&As[buf][k][ty * 4];
            *(float4*)&a[4] = *(const float4*)&As[buf][k][64 + ty * 4];
            *(float4*)&b[0] = *(const float4*)&Bs[buf][k][tx * 4];
            *(float4*)&b[4] = *(const float4*)&Bs[buf][k][64 + tx * 4];
            #pragma unroll
            for (int r = 0; r < 8; r++)
                #pragma unroll
                for (int c = 0; c < 8; c++) acc[r][c] += a[r] * b[c];
        }
        if (t + 1 < nt) { STORE(buf ^ 1); }
        __syncthreads();
    }
    #pragma unroll
    for (int ri = 0; ri < 2; ri++) {
        #pragma unroll
        for (int r = 0; r < 4; r++) {
            int gr = row0 + ri * 64 + ty * 4 + r;
            if (gr >= M) continue;
            #pragma unroll
            for (int ci = 0; ci < 2; ci++) {
                int gc = col0 + ci * 64 + tx * 4;
                float4 v;
                v.x = acc[ri * 4 + r][ci * 4 + 0];
                v.y = acc[ri * 4 + r][ci * 4 + 1];
                v.z = acc[ri * 4 + r][ci * 4 + 2];
                v.w = acc[ri * 4 + r][ci * 4 + 3];
                if (bias) {
                    v.x += bias[gc + 0]; v.y += bias[gc + 1];
                    v.z += bias[gc + 2]; v.w += bias[gc + 3];
                }
                *(float4*)(C + (size_t)gr * N + gc) = v;
            }
        }
    }
    #undef FETCH
    #undef STORE
}

// ---------------- tensor-core split-bf16 GEMM: K=128 fixed ----------------
// C[M,N] = A@B (+bias), A given as hi/lo bf16 [M,128], B as hi/lo bf16 [128,N].
// CTA tile 64x128, warp tile 32x32, mma.m16n8k16, 3-term split (hh + lh + hl).
__device__ __forceinline__ void ldsm4(unsigned& r0, unsigned& r1, unsigned& r2, unsigned& r3,
                                      unsigned addr) {
    asm volatile("ldmatrix.sync.aligned.m8n8.x4.shared.b16 {%0,%1,%2,%3}, [%4];"
                 : "=r"(r0), "=r"(r1), "=r"(r2), "=r"(r3) : "r"(addr));
}
__device__ __forceinline__ void ldsm4t(unsigned& r0, unsigned& r1, unsigned& r2, unsigned& r3,
                                       unsigned addr) {
    asm volatile("ldmatrix.sync.aligned.m8n8.x4.trans.shared.b16 {%0,%1,%2,%3}, [%4];"
                 : "=r"(r0), "=r"(r1), "=r"(r2), "=r"(r3) : "r"(addr));
}
__device__ __forceinline__ void mma16816(float* d, const unsigned* a, const unsigned* b) {
    asm volatile("mma.sync.aligned.m16n8k16.row.col.f32.bf16.bf16.f32 "
                 "{%0,%1,%2,%3}, {%4,%5,%6,%7}, {%8,%9}, {%0,%1,%2,%3};"
                 : "+f"(d[0]), "+f"(d[1]), "+f"(d[2]), "+f"(d[3])
                 : "r"(a[0]), "r"(a[1]), "r"(a[2]), "r"(a[3]), "r"(b[0]), "r"(b[1]));
}

__global__ __launch_bounds__(256) void gemm_tc(
    const __nv_bfloat16* __restrict__ Ah, const __nv_bfloat16* __restrict__ Al,
    const __nv_bfloat16* __restrict__ Bh, const __nv_bfloat16* __restrict__ Bl,
    const float* __restrict__ bias, float* __restrict__ C, int M, int N) {
    // A smem: 64 rows x 128B (8x16B chunks, 4 used per k32), XOR-swizzled
    __shared__ __nv_bfloat16 sAh[64 * 64], sAl[64 * 64];
    __shared__ __nv_bfloat16 sBh[32 * 128], sBl[32 * 128];
    int tid = threadIdx.x, w = tid >> 5, lane = tid & 31;
    int row0 = blockIdx.x * 64, col0 = blockIdx.y * 128;
    int wm = (w >> 2) * 32, wn = (w & 3) * 32;

    unsigned uAh = (unsigned)__cvta_generic_to_shared(sAh);
    unsigned uAl = (unsigned)__cvta_generic_to_shared(sAl);
    unsigned uBh = (unsigned)__cvta_generic_to_shared(sBh);
    unsigned uBl = (unsigned)__cvta_generic_to_shared(sBl);

    float acc[2][4][4];
    #pragma unroll
    for (int m = 0; m < 2; m++)
        #pragma unroll
        for (int n = 0; n < 4; n++)
            #pragma unroll
            for (int q = 0; q < 4; q++) acc[m][n][q] = 0.f;

    // staging thread roles
    int ar = tid >> 2, acg = tid & 3;          // A: row 0..63, 16B-chunk 0..3
    int br = tid >> 3, bcg = (tid & 7) * 2;    // B: k-row 0..31, chunks bcg,bcg+1
    // ldmatrix lane row pattern: lanes 0-7 ->0-7, 8-15 ->8-15, 16-23 ->0-7, 24-31 ->8-15
    int lrow = (lane & 7) | (lane & 8);
    int lsel = lane >> 4;

    for (int kc = 0; kc < 4; kc++) {
        int k0 = kc * 32;
        // ---- stage A chunk ----
        {
            int gr = row0 + ar;
            uint4 vh = make_uint4(0, 0, 0, 0), vl = make_uint4(0, 0, 0, 0);
            if (gr < M) {
                vh = *(const uint4*)(Ah + (size_t)gr * HID + k0 + acg * 8);
                vl = *(const uint4*)(Al + (size_t)gr * HID + k0 + acg * 8);
            }
            int pc = acg ^ (ar & 7);
            *(uint4*)((char*)sAh + ar * 128 + pc * 16) = vh;
            *(uint4*)((char*)sAl + ar * 128 + pc * 16) = vl;
        }
        // ---- stage B chunk ----
        {
            const __nv_bfloat16* bs = Bh + (size_t)(k0 + br) * N + col0;
            uint4 v0 = *(const uint4*)(bs + bcg * 8);
            uint4 v1 = *(const uint4*)(bs + bcg * 8 + 8);
            int p0 = bcg ^ (br & 7), p1 = (bcg + 1) ^ (br & 7);
            *(uint4*)((char*)sBh + br * 256 + p0 * 16) = v0;
            *(uint4*)((char*)sBh + br * 256 + p1 * 16) = v1;
            bs = Bl + (size_t)(k0 + br) * N + col0;
            v0 = *(const uint4*)(bs + bcg * 8);
            v1 = *(const uint4*)(bs + bcg * 8 + 8);
            *(uint4*)((char*)sBl + br * 256 + p0 * 16) = v0;
            *(uint4*)((char*)sBl + br * 256 + p1 * 16) = v1;
        }
        __syncthreads();
        #pragma unroll
        for (int s = 0; s < 2; s++) {
            unsigned ah[2][4], al[2][4], bh[8], bl[8];
            #pragma unroll
            for (int mt = 0; mt < 2; mt++) {
                int r = wm + mt * 16 + lrow;
                int ch = s * 2 + lsel;
                unsigned off = r * 128 + ((ch ^ (r & 7)) * 16);
                ldsm4(ah[mt][0], ah[mt][1], ah[mt][2], ah[mt][3], uAh + off);
                ldsm4(al[mt][0], al[mt][1], al[mt][2], al[mt][3], uAl + off);
            }
            #pragma unroll
            for (int j = 0; j < 2; j++) {
                int kr = s * 16 + lrow;
                int ch = (wn >> 3) + j * 2 + lsel;
                unsigned off = kr * 256 + ((ch ^ (kr & 7)) * 16);
                ldsm4t(bh[j * 4 + 0], bh[j * 4 + 1], bh[j * 4 + 2], bh[j * 4 + 3], uBh + off);
                ldsm4t(bl[j * 4 + 0], bl[j * 4 + 1], bl[j * 4 + 2], bl[j * 4 + 3], uBl + off);
            }
            #pragma unroll
            for (int mt = 0; mt < 2; mt++)
                #pragma unroll
                for (int ng = 0; ng < 4; ng++) {
                    mma16816(acc[mt][ng], ah[mt], &bh[ng * 2]);
                    mma16816(acc[mt][ng], al[mt], &bh[ng * 2]);
                    mma16816(acc[mt][ng], ah[mt], &bl[ng * 2]);
                }
        }
        __syncthreads();
    }
    // ---- epilogue ----
    int cr = lane >> 2, cc = (lane & 3) * 2;
    #pragma unroll
    for (int mt = 0; mt < 2; mt++) {
        #pragma unroll
        for (int half = 0; half < 2; half++) {
            int gr = row0 + wm + mt * 16 + cr + half * 8;
            if (gr >= M) continue;
            #pragma unroll
            for (int ng = 0; ng < 4; ng++) {
                int gc = col0 + wn + ng * 8 + cc;
                float2 v;
                v.x = acc[mt][ng][half * 2 + 0];
                v.y = acc[mt][ng][half * 2 + 1];
                if (bias) { v.x += bias[gc]; v.y += bias[gc + 1]; }
                *(float2*)(C + (size_t)gr * N + gc) = v;
            }
        }
    }
}

// ---------------- fused attention dots ----------------
__global__ void dots_kernel(const float* __restrict__ x, int n, DotArgs da) {
    __shared__ float sw[6 * 1024];
    int tid = threadIdx.x;
    int tot = da.nw * 1024;
    for (int i = tid; i < tot; i += 256) sw[i] = da.w[i >> 10][i & 1023];
    __syncthreads();
    int node = blockIdx.x * 8 + (tid >> 5);
    int lane = tid & 31;
    if (node >= n) return;
    float xv[4];
    #pragma unroll
    for (int i = 0; i < 4; i++) xv[i] = x[(size_t)node * HID + lane + 32 * i];
    for (int j = 0; j < da.nw; j++) {
        float acc[8] = {0,0,0,0,0,0,0,0};
        #pragma unroll
        for (int i = 0; i < 4; i++) {
            const float* wp = &sw[j * 1024 + (lane + 32 * i) * 8];
            #pragma unroll
            for (int h = 0; h < 8; h++) acc[h] += xv[i] * wp[h];
        }
        #pragma unroll
        for (int off = 16; off > 0; off >>= 1)
            #pragma unroll
            for (int h = 0; h < 8; h++) acc[h] += __shfl_xor_sync(FULLMASK, acc[h], off);
        if (lane == 0)
            for (int h = 0; h < da.H; h++) da.out[j][(size_t)node * da.H + h] = acc[h];
    }
}

// ---------------- batched edge attention dots ----------------
__global__ void edge_ae_all(EAArgs ea, const float* __restrict__ Me_base,
                            const float* __restrict__ ce_base, int H) {
    const int Esz[5] = {150000, 100000, 150000, 100000, 100000};
    int t = blockIdx.y;
    int E = Esz[t];
    __shared__ float sMe[256];
    __shared__ float sce[8];
    int tid = threadIdx.x;
    sMe[tid] = Me_base[t * 256 + tid];
    if (tid < 8) sce[tid] = ce_base[t * 8 + tid];
    __syncthreads();
    int e = blockIdx.x * 256 + tid;
    if (e >= E) return;
    const float* er = ea.ea[t] + (size_t)e * 32;
    float acc[8];
    #pragma unroll
    for (int h = 0; h < 8; h++) acc[h] = sce[h];
    #pragma unroll 8
    for (int k = 0; k < 32; k++) {
        float v = er[k];
        #pragma unroll
        for (int h = 0; h < 8; h++) acc[h] += v * sMe[k * 8 + h];
    }
    int pos = g_epos[t * EMAX + e];
    float* out = g_aes + (size_t)t * EMAX * 8;
    for (int h = 0; h < H; h++) out[(size_t)pos * H + h] = acc[h];
}

// ---------------- CSR build ----------------
__global__ void zero_int_kernel(int* p, int n) {
    int i = blockIdx.x * blockDim.x + threadIdx.x;
    if (i < n) p[i] = 0;
}
__global__ void hist_kernel(const int* __restrict__ EI, int E, int* __restrict__ cnt) {
    int e = blockIdx.x * blockDim.x + threadIdx.x;
    if (e < E) atomicAdd(&cnt[EI[E + e]], 1);
}
__global__ void scan_kernel(const int* __restrict__ cnt, int* __restrict__ rowptr, int n) {
    __shared__ int wsum[32];
    __shared__ int sbase;
    int tid = threadIdx.x, lane = tid & 31, wid = tid >> 5;
    if (tid == 0) sbase = 0;
    __syncthreads();
    for (int i0 = 0; i0 < n; i0 += 1024) {
        int i = i0 + tid;
        int v = (i < n) ? cnt[i] : 0;
        int x = v;
        #pragma unroll
        for (int o = 1; o < 32; o <<= 1) {
            int t = __shfl_up_sync(FULLMASK, x, o);
            if (lane >= o) x += t;
        }
        if (lane == 31) wsum[wid] = x;
        __syncthreads();
        if (wid == 0) {
            int s = wsum[lane];
            #pragma unroll
            for (int o = 1; o < 32; o <<= 1) {
                int t = __shfl_up_sync(FULLMASK, s, o);
                if (lane >= o) s += t;
            }
            wsum[lane] = s;
        }
        __syncthreads();
        int excl = x - v + (wid ? wsum[wid - 1] : 0) + sbase;
        if (i < n) rowptr[i] = excl;
        __syncthreads();
        if (tid == 0) sbase += wsum[31];
        __syncthreads();
    }
    if (tid == 0) rowptr[n] = sbase;
}
__global__ void scatter_kernel(const int* __restrict__ EI, int E,
                               const int* __restrict__ rowptr, int* __restrict__ cursor,
                               int* __restrict__ srcs, int* __restrict__ epos) {
    int e = blockIdx.x * blockDim.x + threadIdx.x;
    if (e >= E) return;
    int dst = EI[E + e];
    int pos = rowptr[dst] + atomicAdd(&cursor[dst], 1);
    srcs[pos] = EI[e];
    epos[e] = pos;
}

// ---------------- merged gather: ONE-PASS online softmax (two-pass regressed) ----------------
template <int H>
__global__ void gat_gather_all(GArgs ga) {
    int w = (blockIdx.x * blockDim.x + threadIdx.x) >> 5;
    int lane = threadIdx.x & 31;
    if (w >= NALL) return;
    const int hl = (lane * 4 * H) >> 7;
    int nrel, rels[3], node;
    float4 tot;
    const float* bgp = ga.bg;
    if (w < NOP) {
        node = w; nrel = 3; rels[0] = 0; rels[1] = 2; rels[2] = 3;
        float4 b0 = *(const float4*)(bgp + 0 * HID + lane * 4);
        float4 b2 = *(const float4*)(bgp + 2 * HID + lane * 4);
        float4 b3 = *(const float4*)(bgp + 3 * HID + lane * 4);
        tot = make_float4(b0.x + b2.x + b3.x, b0.y + b2.y + b3.y,
                          b0.z + b2.z + b3.z, b0.w + b2.w + b3.w);
    } else if (w < NOP + NMA) {
        node = w - NOP; nrel = 1; rels[0] = 1;
        tot = *(const float4*)(bgp + 1 * HID + lane * 4);
    } else {
        node = w - NOP - NMA; nrel = 1; rels[0] = 4;
        tot = *(const float4*)(bgp + 4 * HID + lane * 4);
    }
    for (int ri = 0; ri < nrel; ri++) {
        int r = rels[ri];
        const int* rp = g_rowptr + r * (NOP + 1);
        int beg = rp[node], end = rp[node + 1];
        const int* sr = g_srcs + r * EMAX;
        const float* aes = g_aes + (size_t)r * EMAX * 8;
        const float* asb = g_asL + (size_t)r * NOP * 8;
        float adv = (lane < H) ? g_adL[(size_t)r * NOP * 8 + (size_t)node * H + lane] : 0.f;
        const float* xs = ga.xs[r];
        int rs = ga.rs[r];
        float m = -1e30f, den = 0.f;
        float4 acc = make_float4(0.f, 0.f, 0.f, 0.f);
        for (int p = beg; p < end; p++) {
            int s = sr[p];
            float lg = 0.f;
            if (lane < H) {
                lg = asb[(size_t)s * H + lane] + adv + aes[(size_t)p * H + lane];
                lg = lg > 0.f ? lg : 0.2f * lg;
            }
            float le = (H == 1) ? __shfl_sync(FULLMASK, lg, 0)
                                : __shfl_sync(FULLMASK, lg, hl);
            if (le > m) {
                float sc = __expf(m - le);
                acc.x *= sc; acc.y *= sc; acc.z *= sc; acc.w *= sc;
                den *= sc;
                m = le;
            }
            float wv = __expf(le - m);
            den += wv;
            const float4 xv = *(const float4*)(xs + (size_t)s * rs + lane * 4);
            acc.x += wv * xv.x; acc.y += wv * xv.y;
            acc.z += wv * xv.z; acc.w += wv * xv.w;
        }
        float inv = 1.f / (den + 1e-16f);
        tot.x += acc.x * inv; tot.y += acc.y * inv;
        tot.z += acc.z * inv; tot.w += acc.w * inv;
    }
    *(float4*)(g_agg + (size_t)w * HID + lane * 4) = tot;
}

// ---------------- BN ----------------
__global__ void bn_stats_kernel() {
    const int offs[3] = {0, NOP, NOP + NMA};
    const int cnts[3] = {NOP, NMA, NJOB};
    int type = blockIdx.y;
    int col = threadIdx.x;
    int N = cnts[type], off = offs[type];
    double s = 0.0, s2 = 0.0;
    for (int r = blockIdx.x; r < N; r += 64) {
        float v = g_agg[(size_t)(off + r) * HID + col];
        s += (double)v;
        s2 += (double)v * (double)v;
    }
    g_part[((0 * 3 + type) * 64 + blockIdx.x) * HID + col] = s;
    g_part[((1 * 3 + type) * 64 + blockIdx.x) * HID + col] = s2;
}

__global__ void bn_finalize_kernel(const float* __restrict__ gamma,
                                   const float* __restrict__ beta, int layer) {
    const int cnts[3] = {NOP, NMA, NJOB};
    int idx = threadIdx.x + blockIdx.x * blockDim.x;
    if (idx >= 3 * HID) return;
    int type = idx / HID, col = idx % HID;
    double s = 0.0, s2 = 0.0;
    for (int c = 0; c < 64; c++) {
        s  += g_part[((0 * 3 + type) * 64 + c) * HID + col];
        s2 += g_part[((1 * 3 + type) * 64 + c) * HID + col];
    }
    double N = (double)cnts[type];
    double mu = s / N;
    double var = s2 / N - mu * mu;
    if (var < 0.0) var = 0.0;
    float g = gamma[layer * 3 * HID + type * HID + col];
    float b = beta[layer * 3 * HID + type * HID + col];
    float sc = g * rsqrtf((float)var + 1e-5f);
    g_scale[idx] = sc;
    g_shift[idx] = b - (float)mu * sc;
}

// BN apply + relu + residual; also refresh bf16 hi/lo split of g_x
__global__ void bn_apply_kernel(int layer) {
    int idx = blockIdx.x * blockDim.x + threadIdx.x;
    if (idx >= NALL * HID) return;
    int row = idx / HID, col = idx % HID;
    int type = (row < NOP) ? 0 : ((row < NOP + NMA) ? 1 : 2);
    float v = g_agg[idx] * g_scale[type * HID + col] + g_shift[type * HID + col];
    if (layer < NLAYERS - 1) v = fmaxf(v, 0.f);
    float nx = g_x[idx] + v;
    g_x[idx] = nx;
    __nv_bfloat16 hi = __float2bfloat16(nx);
    g_xh[idx] = hi;
    g_xl[idx] = __float2bfloat16(nx - __bfloat162float(hi));
}

// ---------------- launch ----------------
extern "C" void kernel_launch(void* const* d_in, const int* in_sizes, int n_in,
                              void* d_out, int out_size) {
    const float* x_op  = (const float*)d_in[0];
    const float* x_ma  = (const float*)d_in[1];
    const float* x_job = (const float*)d_in[2];

    const int* EI[5];
    const float* EA[5];
    bool interleaved = (in_sizes[4] > 1000000);
    if (interleaved) {
        for (int t = 0; t < 5; t++) {
            EI[t] = (const int*)d_in[3 + 2 * t];
            EA[t] = (const float*)d_in[4 + 2 * t];
        }
    } else {
        for (int t = 0; t < 5; t++) {
            EI[t] = (const int*)d_in[3 + t];
            EA[t] = (const float*)d_in[8 + t];
        }
    }

    const float* Wn_op = (const float*)d_in[13];
    const float* bn_op = (const float*)d_in[14];
    const float* Wn_ma = (const float*)d_in[15];
    const float* bn_ma = (const float*)d_in[16];
    const float* Wn_job = (const float*)d_in[17];
    const float* bn_job = (const float*)d_in[18];
    const float* We_proj = (const float*)d_in[19];
    const float* be_proj = (const float*)d_in[20];
    const float* Wg    = (const float*)d_in[21];
    const float* att_s = (const float*)d_in[22];
    const float* att_d = (const float*)d_in[23];
    const float* Wge   = (const float*)d_in[24];
    const float* att_e = (const float*)d_in[25];
    const float* bg    = (const float*)d_in[26];
    const float* gamma = (const float*)d_in[27];
    const float* beta  = (const float*)d_in[28];
    const float* Wo    = (const float*)d_in[29];
    const float* bo    = (const float*)d_in[30];

    static const int Esz[5]  = {150000, 100000, 150000, 100000, 100000};
    static const int Tdst[5] = {0, 1, 0, 0, 2};
    static const int cntn[3] = {NOP, NMA, NJOB};

    float* gx;    cudaGetSymbolAddress((void**)&gx, g_x);
    float* gxs3;  cudaGetSymbolAddress((void**)&gxs3, g_xs3);
    float* gxsm;  cudaGetSymbolAddress((void**)&gxsm, g_xsm);
    float* gxsj;  cudaGetSymbolAddress((void**)&gxsj, g_xsj);
    float* gasL;  cudaGetSymbolAddress((void**)&gasL, g_asL);
    float* gadL;  cudaGetSymbolAddress((void**)&gadL, g_adL);
    float* gws;   cudaGetSymbolAddress((void**)&gws, g_ws);
    float* gwd;   cudaGetSymbolAddress((void**)&gwd, g_wd);
    float* gMe;   cudaGetSymbolAddress((void**)&gMe, g_Me);
    float* gce;   cudaGetSymbolAddress((void**)&gce, g_ce);
    float* gWcat; cudaGetSymbolAddress((void**)&gWcat, g_Wcat);
    int* grp;     cudaGetSymbolAddress((void**)&grp, g_rowptr);
    int* gsrc;    cudaGetSymbolAddress((void**)&gsrc, g_srcs);
    int* gep;     cudaGetSymbolAddress((void**)&gep, g_epos);
    int* gcnt;    cudaGetSymbolAddress((void**)&gcnt, g_cnt);
    int* gcur;    cudaGetSymbolAddress((void**)&gcur, g_cursor);
    __nv_bfloat16 *gxh, *gxl, *gWcH, *gWcL, *gWmH, *gWmL, *gWjH, *gWjL, *gWoH, *gWoL;
    cudaGetSymbolAddress((void**)&gxh, g_xh);
    cudaGetSymbolAddress((void**)&gxl, g_xl);
    cudaGetSymbolAddress((void**)&gWcH, g_WcatH);
    cudaGetSymbolAddress((void**)&gWcL, g_WcatL);
    cudaGetSymbolAddress((void**)&gWmH, g_WsmH);
    cudaGetSymbolAddress((void**)&gWmL, g_WsmL);
    cudaGetSymbolAddress((void**)&gWjH, g_WsjH);
    cudaGetSymbolAddress((void**)&gWjL, g_WsjL);
    cudaGetSymbolAddress((void**)&gWoH, g_WoH);
    cudaGetSymbolAddress((void**)&gWoL, g_WoL);

    // ---- prep: folds, Wcat pack, weight splits ----
    fold_kernel<<<15, 128>>>(Wg, att_s, att_d, Wge, att_e, We_proj, be_proj);
    pack_wcat<<<(3 * HID * 384 + 255) / 256, 256>>>(Wg);
    cvt_split<<<(3 * HID * 384 + 255) / 256, 256>>>(gWcat, gWcH, gWcL, 3 * HID * 384);
    for (int i = 0; i < NLAYERS; i++) {
        cvt_split<<<(HID * HID + 255) / 256, 256>>>(Wg + (size_t)(i * 5 + 2) * HID * HID,
                                                    gWmH + (size_t)i * HID * HID,
                                                    gWmL + (size_t)i * HID * HID, HID * HID);
        cvt_split<<<(HID * HID + 255) / 256, 256>>>(Wg + (size_t)(i * 5 + 3) * HID * HID,
                                                    gWjH + (size_t)i * HID * HID,
                                                    gWjL + (size_t)i * HID * HID, HID * HID);
    }
    cvt_split<<<(HID * HID + 255) / 256, 256>>>(Wo, gWoH, gWoL, HID * HID);

    // ---- input projections (fp32) + initial x split ----
    gemm3<<<dim3((NOP + 127) / 128, 1), 256>>>(x_op, Wn_op, bn_op, gx, NOP, 64, 128);
    gemm3<<<dim3((NMA + 127) / 128, 1), 256>>>(x_ma, Wn_ma, bn_ma, gx + (size_t)NOP * HID, NMA, 32, 128);
    gemm3<<<dim3((NJOB + 127) / 128, 1), 256>>>(x_job, Wn_job, bn_job, gx + (size_t)(NOP + NMA) * HID, NJOB, 16, 128);
    cvt_split<<<(NALL * HID + 255) / 256, 256>>>(gx, gxh, gxl, NALL * HID);

    // ---- CSR build ----
    for (int t = 0; t < 5; t++) {
        int E = Esz[t];
        int ndst = cntn[Tdst[t]];
        zero_int_kernel<<<(ndst + 255) / 256, 256>>>(gcnt, ndst);
        hist_kernel<<<(E + 255) / 256, 256>>>(EI[t], E, gcnt);
        scan_kernel<<<1, 1024>>>(gcnt, grp + t * (NOP + 1), ndst);
        zero_int_kernel<<<(ndst + 255) / 256, 256>>>(gcur, ndst);
        scatter_kernel<<<(E + 255) / 256, 256>>>(EI[t], E, grp + t * (NOP + 1), gcur,
                                                 gsrc + t * EMAX, gep + t * EMAX);
    }

    EAArgs eaa;
    for (int t = 0; t < 5; t++) eaa.ea[t] = EA[t];

    // ---- layers ----
    for (int i = 0; i < NLAYERS; i++) {
        int H = (i < NLAYERS - 1) ? 8 : 1;
        int b = i * 5;
        // tensor-core src projections (K=128)
        gemm_tc<<<dim3((NOP + 63) / 64, 3), 256>>>(gxh, gxl,
                                                   gWcH + (size_t)i * HID * 384,
                                                   gWcL + (size_t)i * HID * 384,
                                                   nullptr, gxs3, NOP, 384);
        gemm_tc<<<dim3((NMA + 63) / 64, 1), 256>>>(gxh + (size_t)NOP * HID, gxl + (size_t)NOP * HID,
                                                   gWmH + (size_t)i * HID * HID,
                                                   gWmL + (size_t)i * HID * HID,
                                                   nullptr, gxsm, NMA, 128);
        gemm_tc<<<dim3((NJOB + 63) / 64, 1), 256>>>(gxh + (size_t)(NOP + NMA) * HID,
                                                    gxl + (size_t)(NOP + NMA) * HID,
                                                    gWjH + (size_t)i * HID * HID,
                                                    gWjL + (size_t)i * HID * HID,
                                                    nullptr, gxsj, NJOB, 128);
        // fused attention dots
        {
            DotArgs da;
            da.w[0] = gws + (b + 0) * 1024; da.out[0] = gasL + (size_t)0 * NOP * 8;
            da.w[1] = gws + (b + 1) * 1024; da.out[1] = gasL + (size_t)1 * NOP * 8;
            da.w[2] = gws + (b + 4) * 1024; da.out[2] = gasL + (size_t)4 * NOP * 8;
            da.w[3] = gwd + (b + 0) * 1024; da.out[3] = gadL + (size_t)0 * NOP * 8;
            da.w[4] = gwd + (b + 2) * 1024; da.out[4] = gadL + (size_t)2 * NOP * 8;
            da.w[5] = gwd + (b + 3) * 1024; da.out[5] = gadL + (size_t)3 * NOP * 8;
            da.nw = 6; da.H = H;
            dots_kernel<<<(NOP + 7) / 8, 256>>>(gx, NOP, da);
        }
        {
            DotArgs da;
            da.w[0] = gws + (b + 2) * 1024; da.out[0] = gasL + (size_t)2 * NOP * 8;
            da.w[1] = gwd + (b + 1) * 1024; da.out[1] = gadL + (size_t)1 * NOP * 8;
            da.nw = 2; da.H = H;
            dots_kernel<<<(NMA + 7) / 8, 256>>>(gx + (size_t)NOP * HID, NMA, da);
        }
        {
            DotArgs da;
            da.w[0] = gws + (b + 3) * 1024; da.out[0] = gasL + (size_t)3 * NOP * 8;
            da.w[1] = gwd + (b + 4) * 1024; da.out[1] = gadL + (size_t)4 * NOP * 8;
            da.nw = 2; da.H = H;
            dots_kernel<<<(NJOB + 7) / 8, 256>>>(gx + (size_t)(NOP + NMA) * HID, NJOB, da);
        }
        edge_ae_all<<<dim3((EMAX + 255) / 256, 5), 256>>>(eaa, gMe + b * 256, gce + b * 8, H);
        {
            GArgs ga;
            ga.xs[0] = gxs3;        ga.rs[0] = 384;
            ga.xs[1] = gxs3 + 128;  ga.rs[1] = 384;
            ga.xs[2] = gxsm;        ga.rs[2] = 128;
            ga.xs[3] = gxsj;        ga.rs[3] = 128;
            ga.xs[4] = gxs3 + 256;  ga.rs[4] = 384;
            ga.bg = bg + i * 5 * HID;
            if (H == 8)
                gat_gather_all<8><<<(NALL * 32 + 255) / 256, 256>>>(ga);
            else
                gat_gather_all<1><<<(NALL * 32 + 255) / 256, 256>>>(ga);
        }
        bn_stats_kernel<<<dim3(64, 3), 128>>>();
        bn_finalize_kernel<<<2, 256>>>(gamma, beta, i);
        bn_apply_kernel<<<(NALL * HID + 255) / 256, 256>>>(i);
    }

    // ---- output projection (tensor core) ----
    gemm_tc<<<dim3((NOP + 63) / 64, 1), 256>>>(gxh, gxl, gWoH, gWoL, bo, (float*)d_out, NOP, 128);
}

// round 12
// speedup vs baseline: 1.1526x; 1.0026x over previous
#include <cuda_runtime.h>
#include <cuda_bf16.h>
#include <math.h>

#define HID 128
#define NOP 50000
#define NMA 1000
#define NJOB 5000
#define NALL 56000
#define NLAYERS 3
#define EMAX 150000
#define FULLMASK 0xffffffffu

// ---------------- device scratch ----------------
__device__ float g_x[NALL * HID];
__device__ float g_agg[NALL * HID];
__device__ float g_xs3[NOP * 384];
__device__ float g_xsm[NMA * HID];
__device__ float g_xsj[NJOB * HID];
__device__ float g_asL[5 * NOP * 8];
__device__ float g_adL[5 * NOP * 8];
__device__ float g_aes[5 * EMAX * 8];
__device__ float g_ws[15 * HID * 8];
__device__ float g_wd[15 * HID * 8];
__device__ float g_Me[15 * 32 * 8];
__device__ float g_ce[15 * 8];
__device__ float g_Wcat[3 * HID * 384];
// bf16 split operands
__device__ __nv_bfloat16 g_xh[NALL * HID];
__device__ __nv_bfloat16 g_xl[NALL * HID];
__device__ __nv_bfloat16 g_WcatH[3 * HID * 384];
__device__ __nv_bfloat16 g_WcatL[3 * HID * 384];
__device__ __nv_bfloat16 g_WsmH[3 * HID * HID];
__device__ __nv_bfloat16 g_WsmL[3 * HID * HID];
__device__ __nv_bfloat16 g_WsjH[3 * HID * HID];
__device__ __nv_bfloat16 g_WsjL[3 * HID * HID];
__device__ __nv_bfloat16 g_WoH[HID * HID];
__device__ __nv_bfloat16 g_WoL[HID * HID];
// CSR
__device__ int g_rowptr[5 * (NOP + 1)];
__device__ int g_srcs[5 * EMAX];
__device__ int g_epos[5 * EMAX];
__device__ int g_cnt[NOP];
__device__ int g_cursor[NOP];
// BN
__device__ double g_part[2 * 3 * 64 * HID];
__device__ float g_scale[3 * HID];
__device__ float g_shift[3 * HID];

struct DotArgs { const float* w[6]; float* out[6]; int nw; int H; };
struct EAArgs  { const float* ea[5]; };
struct GArgs   { const float* xs[5]; int rs[5]; const float* bg; };

// ---------------- fold kernel ----------------
__global__ void fold_kernel(const float* __restrict__ Wg, const float* __restrict__ att_s,
                            const float* __restrict__ att_d, const float* __restrict__ Wge,
                            const float* __restrict__ att_e, const float* __restrict__ We_proj,
                            const float* __restrict__ be_proj) {
    int slot = blockIdx.x;
    int i = slot / 5, t = slot % 5;
    int H = (i < NLAYERS - 1) ? 8 : 1;
    int C = HID / H;
    int k = threadIdx.x;
    const float* Wg_  = Wg  + (size_t)slot * HID * HID;
    const float* Wge_ = Wge + (size_t)slot * HID * HID;
    const float* as_  = att_s + slot * HID;
    const float* ad_  = att_d + slot * HID;
    const float* ae_  = att_e + slot * HID;

    float ws[8] = {0,0,0,0,0,0,0,0};
    float wd[8] = {0,0,0,0,0,0,0,0};
    float we[8] = {0,0,0,0,0,0,0,0};
    for (int j = 0; j < HID; j++) {
        int h = j / C;
        float w1 = Wg_[k * HID + j];
        ws[h] += w1 * as_[j];
        wd[h] += w1 * ad_[j];
        float w2 = Wge_[k * HID + j];
        we[h] += w2 * ae_[j];
    }
    #pragma unroll
    for (int h = 0; h < 8; h++) {
        g_ws[slot * HID * 8 + k * 8 + h] = ws[h];
        g_wd[slot * HID * 8 + k * 8 + h] = wd[h];
    }
    __shared__ float wef[HID * 8];
    #pragma unroll
    for (int h = 0; h < 8; h++) wef[k * 8 + h] = we[h];
    __syncthreads();

    if (k < 32) {
        const float* Wep = We_proj + (size_t)t * 32 * HID + (size_t)k * HID;
        float me[8] = {0,0,0,0,0,0,0,0};
        for (int j = 0; j < HID; j++) {
            float v = Wep[j];
            #pragma unroll
            for (int h = 0; h < 8; h++) me[h] += v * wef[j * 8 + h];
        }
        #pragma unroll
        for (int h = 0; h < 8; h++) g_Me[slot * 32 * 8 + k * 8 + h] = me[h];
    }
    if (k == 32) {
        const float* bep = be_proj + t * HID;
        float ce[8] = {0,0,0,0,0,0,0,0};
        for (int j = 0; j < HID; j++) {
            float v = bep[j];
            #pragma unroll
            for (int h = 0; h < 8; h++) ce[h] += v * wef[j * 8 + h];
        }
        #pragma unroll
        for (int h = 0; h < 8; h++) g_ce[slot * 8 + h] = ce[h];
    }
}

// ---------------- pack Wcat ----------------
__global__ void pack_wcat(const float* __restrict__ Wg) {
    int idx = blockIdx.x * blockDim.x + threadIdx.x;
    if (idx >= 3 * HID * 384) return;
    int i = idx / (HID * 384);
    int rem = idx % (HID * 384);
    int k = rem / 384, c = rem % 384;
    int r = c / 128, j = c % 128;
    const int tsel[3] = {0, 1, 4};
    g_Wcat[idx] = Wg[(((size_t)(i * 5 + tsel[r])) * HID + k) * HID + j];
}

// ---------------- split fp32 -> bf16 hi/lo ----------------
__global__ void cvt_split(const float* __restrict__ src, __nv_bfloat16* __restrict__ h,
                          __nv_bfloat16* __restrict__ l, int n) {
    int i = blockIdx.x * blockDim.x + threadIdx.x;
    if (i >= n) return;
    float v = src[i];
    __nv_bfloat16 hi = __float2bfloat16(v);
    h[i] = hi;
    l[i] = __float2bfloat16(v - __bfloat162float(hi));
}

// ---------------- fp32 SGEMM for small-K input projections (+ optional bf16 split out) ----------------
__global__ __launch_bounds__(256, 2) void gemm3(const float* __restrict__ A,
                                                const float* __restrict__ B,
                                                const float* __restrict__ bias,
                                                float* __restrict__ C,
                                                __nv_bfloat16* __restrict__ Ch,
                                                __nv_bfloat16* __restrict__ Cl,
                                                int M, int K, int N) {
    __shared__ float As[2][16][132];
    __shared__ float Bs[2][16][128];
    int tid = threadIdx.x;
    int tx = tid & 15, ty = tid >> 4;
    int row0 = blockIdx.x * 128, col0 = blockIdx.y * 128;
    int ar0 = tid >> 2, ak0 = (tid & 3) * 4;
    int bk0 = tid >> 5, bc0 = (tid & 31) * 4;
    float4 pa[2], pb[2];

    #define FETCH(kk)                                                             \
        _Pragma("unroll")                                                         \
        for (int i = 0; i < 2; i++) {                                             \
            int gr = row0 + ar0 + i * 64;                                         \
            pa[i] = make_float4(0.f, 0.f, 0.f, 0.f);                              \
            if (gr < M) pa[i] = *(const float4*)(A + (size_t)gr * K + (kk) + ak0);\
            pb[i] = *(const float4*)(B + (size_t)((kk) + bk0 + i * 8) * N + col0 + bc0); \
        }
    #define STORE(buf)                                                            \
        _Pragma("unroll")                                                         \
        for (int i = 0; i < 2; i++) {                                             \
            int ar = ar0 + i * 64;                                                \
            As[buf][ak0 + 0][ar] = pa[i].x;  As[buf][ak0 + 1][ar] = pa[i].y;      \
            As[buf][ak0 + 2][ar] = pa[i].z;  As[buf][ak0 + 3][ar] = pa[i].w;      \
            *(float4*)&Bs[buf][bk0 + i * 8][bc0] = pb[i];                         \
        }

    FETCH(0); STORE(0); __syncthreads();

    float acc[8][8];
    #pragma unroll
    for (int r = 0; r < 8; r++)
        #pragma unroll
        for (int c = 0; c < 8; c++) acc[r][c] = 0.f;

    int nt = K >> 4;
    for (int t = 0; t < nt; t++) {
        int buf = t & 1;
        if (t + 1 < nt) { FETCH((t + 1) << 4); }
        #pragma unroll
        for (int k = 0; k < 16; k++) {
            float a[8], b[8];
            *(float4*)&a[0] = *(const float4*)&As[buf][k][ty * 4];
            *(float4*)&a[4] = *(const float4*)&As[buf][k][64 + ty * 4];
            *(float4*)&b[0] = *(const float4*)&Bs[buf][k][tx * 4];
            *(float4*)&b[4] = *(const float4*)&Bs[buf][k][64 + tx * 4];
            #pragma unroll
            for (int r = 0; r < 8; r++)
                #pragma unroll
                for (int c = 0; c < 8; c++) acc[r][c] += a[r] * b[c];
        }
        if (t + 1 < nt) { STORE(buf ^ 1); }
        __syncthreads();
    }
    #pragma unroll
    for (int ri = 0; ri < 2; ri++) {
        #pragma unroll
        for (int r = 0; r < 4; r++) {
            int gr = row0 + ri * 64 + ty * 4 + r;
            if (gr >= M) continue;
            #pragma unroll
            for (int ci = 0; ci < 2; ci++) {
                int gc = col0 + ci * 64 + tx * 4;
                float4 v;
                v.x = acc[ri * 4 + r][ci * 4 + 0];
                v.y = acc[ri * 4 + r][ci * 4 + 1];
                v.z = acc[ri * 4 + r][ci * 4 + 2];
                v.w = acc[ri * 4 + r][ci * 4 + 3];
                if (bias) {
                    v.x += bias[gc + 0]; v.y += bias[gc + 1];
                    v.z += bias[gc + 2]; v.w += bias[gc + 3];
                }
                *(float4*)(C + (size_t)gr * N + gc) = v;
                if (Ch) {
                    float vv[4] = {v.x, v.y, v.z, v.w};
                    #pragma unroll
                    for (int q = 0; q < 4; q++) {
                        __nv_bfloat16 hi = __float2bfloat16(vv[q]);
                        Ch[(size_t)gr * N + gc + q] = hi;
                        Cl[(size_t)gr * N + gc + q] = __float2bfloat16(vv[q] - __bfloat162float(hi));
                    }
                }
            }
        }
    }
    #undef FETCH
    #undef STORE
}

// ---------------- tensor-core split-bf16 GEMM v2: full K=128 staged, one sync ----------------
__device__ __forceinline__ void ldsm4(unsigned& r0, unsigned& r1, unsigned& r2, unsigned& r3,
                                      unsigned addr) {
    asm volatile("ldmatrix.sync.aligned.m8n8.x4.shared.b16 {%0,%1,%2,%3}, [%4];"
                 : "=r"(r0), "=r"(r1), "=r"(r2), "=r"(r3) : "r"(addr));
}
__device__ __forceinline__ void ldsm4t(unsigned& r0, unsigned& r1, unsigned& r2, unsigned& r3,
                                       unsigned addr) {
    asm volatile("ldmatrix.sync.aligned.m8n8.x4.trans.shared.b16 {%0,%1,%2,%3}, [%4];"
                 : "=r"(r0), "=r"(r1), "=r"(r2), "=r"(r3) : "r"(addr));
}
__device__ __forceinline__ void mma16816(float* d, const unsigned* a, const unsigned* b) {
    asm volatile("mma.sync.aligned.m16n8k16.row.col.f32.bf16.bf16.f32 "
                 "{%0,%1,%2,%3}, {%4,%5,%6,%7}, {%8,%9}, {%0,%1,%2,%3};"
                 : "+f"(d[0]), "+f"(d[1]), "+f"(d[2]), "+f"(d[3])
                 : "r"(a[0]), "r"(a[1]), "r"(a[2]), "r"(a[3]), "r"(b[0]), "r"(b[1]));
}

// smem layout (dynamic, 96KB): sAh[64*128] sAl[64*128] sBh[128*128] sBl[128*128]
#define TC2_SMEM (96 * 1024)
__global__ __launch_bounds__(256) void gemm_tc2(
    const __nv_bfloat16* __restrict__ Ah, const __nv_bfloat16* __restrict__ Al,
    const __nv_bfloat16* __restrict__ Bh, const __nv_bfloat16* __restrict__ Bl,
    const float* __restrict__ bias, float* __restrict__ C, int M, int N) {
    extern __shared__ char smdyn[];
    char* sAh = smdyn;                 // 64 rows * 256B
    char* sAl = sAh + 64 * 256;
    char* sBh = sAl + 64 * 256;        // 128 rows * 256B
    char* sBl = sBh + 128 * 256;
    int tid = threadIdx.x, w = tid >> 5, lane = tid & 31;
    int row0 = blockIdx.x * 64, col0 = blockIdx.y * 128;
    int wm = (w >> 2) * 32, wn = (w & 3) * 32;
    unsigned uAh = (unsigned)__cvta_generic_to_shared(sAh);
    unsigned uAl = (unsigned)__cvta_generic_to_shared(sAl);
    unsigned uBh = (unsigned)__cvta_generic_to_shared(sBh);
    unsigned uBl = (unsigned)__cvta_generic_to_shared(sBl);

    // stage A: 64 rows, 4 threads/row, 4 chunks each
    {
        int row = tid >> 2, gr = row0 + row;
        #pragma unroll
        for (int c = 0; c < 4; c++) {
            int ch = (tid & 3) * 4 + c;
            uint4 vh = make_uint4(0, 0, 0, 0), vl = make_uint4(0, 0, 0, 0);
            if (gr < M) {
                vh = *(const uint4*)(Ah + (size_t)gr * HID + ch * 8);
                vl = *(const uint4*)(Al + (size_t)gr * HID + ch * 8);
            }
            int pc = ch ^ (row & 7);
            *(uint4*)(sAh + row * 256 + pc * 16) = vh;
            *(uint4*)(sAl + row * 256 + pc * 16) = vl;
        }
    }
    // stage B: 128 rows, 2 threads/row, 8 chunks each
    {
        int row = tid >> 1;
        #pragma unroll
        for (int c = 0; c < 8; c++) {
            int ch = (tid & 1) * 8 + c;
            uint4 vh = *(const uint4*)(Bh + (size_t)row * N + col0 + ch * 8);
            uint4 vl = *(const uint4*)(Bl + (size_t)row * N + col0 + ch * 8);
            int pc = ch ^ (row & 7);
            *(uint4*)(sBh + row * 256 + pc * 16) = vh;
            *(uint4*)(sBl + row * 256 + pc * 16) = vl;
        }
    }
    __syncthreads();

    float acc[2][4][4];
    #pragma unroll
    for (int m = 0; m < 2; m++)
        #pragma unroll
        for (int n = 0; n < 4; n++)
            #pragma unroll
            for (int q = 0; q < 4; q++) acc[m][n][q] = 0.f;

    int lrow = (lane & 7) | (lane & 8);
    int lsel = lane >> 4;
    #pragma unroll
    for (int k16 = 0; k16 < 8; k16++) {
        unsigned ah[2][4], al[2][4], bh[8], bl[8];
        #pragma unroll
        for (int mt = 0; mt < 2; mt++) {
            int r = wm + mt * 16 + lrow;
            int ch = k16 * 2 + lsel;
            unsigned off = r * 256 + ((ch ^ (r & 7)) * 16);
            ldsm4(ah[mt][0], ah[mt][1], ah[mt][2], ah[mt][3], uAh + off);
            ldsm4(al[mt][0], al[mt][1], al[mt][2], al[mt][3], uAl + off);
        }
        #pragma unroll
        for (int j = 0; j < 2; j++) {
            int kr = k16 * 16 + lrow;
            int ch = (wn >> 3) + j * 2 + lsel;
            unsigned off = kr * 256 + ((ch ^ (kr & 7)) * 16);
            ldsm4t(bh[j * 4 + 0], bh[j * 4 + 1], bh[j * 4 + 2], bh[j * 4 + 3], uBh + off);
            ldsm4t(bl[j * 4 + 0], bl[j * 4 + 1], bl[j * 4 + 2], bl[j * 4 + 3], uBl + off);
        }
        #pragma unroll
        for (int mt = 0; mt < 2; mt++)
            #pragma unroll
            for (int ng = 0; ng < 4; ng++) {
                mma16816(acc[mt][ng], ah[mt], &bh[ng * 2]);
                mma16816(acc[mt][ng], al[mt], &bh[ng * 2]);
                mma16816(acc[mt][ng], ah[mt], &bl[ng * 2]);
            }
    }
    int cr = lane >> 2, cc = (lane & 3) * 2;
    #pragma unroll
    for (int mt = 0; mt < 2; mt++) {
        #pragma unroll
        for (int half = 0; half < 2; half++) {
            int gr = row0 + wm + mt * 16 + cr + half * 8;
            if (gr >= M) continue;
            #pragma unroll
            for (int ng = 0; ng < 4; ng++) {
                int gc = col0 + wn + ng * 8 + cc;
                float2 v;
                v.x = acc[mt][ng][half * 2 + 0];
                v.y = acc[mt][ng][half * 2 + 1];
                if (bias) { v.x += bias[gc]; v.y += bias[gc + 1]; }
                *(float2*)(C + (size_t)gr * N + gc) = v;
            }
        }
    }
}

// ---------------- fused attention dots ----------------
__global__ void dots_kernel(const float* __restrict__ x, int n, DotArgs da) {
    __shared__ float sw[6 * 1024];
    int tid = threadIdx.x;
    int tot = da.nw * 1024;
    for (int i = tid; i < tot; i += 256) sw[i] = da.w[i >> 10][i & 1023];
    __syncthreads();
    int node = blockIdx.x * 8 + (tid >> 5);
    int lane = tid & 31;
    if (node >= n) return;
    float xv[4];
    #pragma unroll
    for (int i = 0; i < 4; i++) xv[i] = x[(size_t)node * HID + lane + 32 * i];
    for (int j = 0; j < da.nw; j++) {
        float acc[8] = {0,0,0,0,0,0,0,0};
        #pragma unroll
        for (int i = 0; i < 4; i++) {
            const float* wp = &sw[j * 1024 + (lane + 32 * i) * 8];
            #pragma unroll
            for (int h = 0; h < 8; h++) acc[h] += xv[i] * wp[h];
        }
        #pragma unroll
        for (int off = 16; off > 0; off >>= 1)
            #pragma unroll
            for (int h = 0; h < 8; h++) acc[h] += __shfl_xor_sync(FULLMASK, acc[h], off);
        if (lane == 0)
            for (int h = 0; h < da.H; h++) da.out[j][(size_t)node * da.H + h] = acc[h];
    }
}

// ---------------- batched edge attention dots ----------------
__global__ void edge_ae_all(EAArgs ea, const float* __restrict__ Me_base,
                            const float* __restrict__ ce_base, int H) {
    const int Esz[5] = {150000, 100000, 150000, 100000, 100000};
    int t = blockIdx.y;
    int E = Esz[t];
    __shared__ float sMe[256];
    __shared__ float sce[8];
    int tid = threadIdx.x;
    sMe[tid] = Me_base[t * 256 + tid];
    if (tid < 8) sce[tid] = ce_base[t * 8 + tid];
    __syncthreads();
    int e = blockIdx.x * 256 + tid;
    if (e >= E) return;
    const float* er = ea.ea[t] + (size_t)e * 32;
    float acc[8];
    #pragma unroll
    for (int h = 0; h < 8; h++) acc[h] = sce[h];
    #pragma unroll 8
    for (int k = 0; k < 32; k++) {
        float v = er[k];
        #pragma unroll
        for (int h = 0; h < 8; h++) acc[h] += v * sMe[k * 8 + h];
    }
    int pos = g_epos[t * EMAX + e];
    float* out = g_aes + (size_t)t * EMAX * 8;
    for (int h = 0; h < H; h++) out[(size_t)pos * H + h] = acc[h];
}

// ---------------- CSR build ----------------
__global__ void zero_int_kernel(int* p, int n) {
    int i = blockIdx.x * blockDim.x + threadIdx.x;
    if (i < n) p[i] = 0;
}
__global__ void hist_kernel(const int* __restrict__ EI, int E, int* __restrict__ cnt) {
    int e = blockIdx.x * blockDim.x + threadIdx.x;
    if (e < E) atomicAdd(&cnt[EI[E + e]], 1);
}
__global__ void scan_kernel(const int* __restrict__ cnt, int* __restrict__ rowptr, int n) {
    __shared__ int wsum[32];
    __shared__ int sbase;
    int tid = threadIdx.x, lane = tid & 31, wid = tid >> 5;
    if (tid == 0) sbase = 0;
    __syncthreads();
    for (int i0 = 0; i0 < n; i0 += 1024) {
        int i = i0 + tid;
        int v = (i < n) ? cnt[i] : 0;
        int x = v;
        #pragma unroll
        for (int o = 1; o < 32; o <<= 1) {
            int t = __shfl_up_sync(FULLMASK, x, o);
            if (lane >= o) x += t;
        }
        if (lane == 31) wsum[wid] = x;
        __syncthreads();
        if (wid == 0) {
            int s = wsum[lane];
            #pragma unroll
            for (int o = 1; o < 32; o <<= 1) {
                int t = __shfl_up_sync(FULLMASK, s, o);
                if (lane >= o) s += t;
            }
            wsum[lane] = s;
        }
        __syncthreads();
        int excl = x - v + (wid ? wsum[wid - 1] : 0) + sbase;
        if (i < n) rowptr[i] = excl;
        __syncthreads();
        if (tid == 0) sbase += wsum[31];
        __syncthreads();
    }
    if (tid == 0) rowptr[n] = sbase;
}
__global__ void scatter_kernel(const int* __restrict__ EI, int E,
                               const int* __restrict__ rowptr, int* __restrict__ cursor,
                               int* __restrict__ srcs, int* __restrict__ epos) {
    int e = blockIdx.x * blockDim.x + threadIdx.x;
    if (e >= E) return;
    int dst = EI[E + e];
    int pos = rowptr[dst] + atomicAdd(&cursor[dst], 1);
    srcs[pos] = EI[e];
    epos[e] = pos;
}

// ---------------- merged gather (op + job nodes; machine handled separately) ----------------
template <int H>
__global__ void gat_gather_all(GArgs ga) {
    int w = (blockIdx.x * blockDim.x + threadIdx.x) >> 5;
    int lane = threadIdx.x & 31;
    if (w >= NALL) return;
    const int hl = (lane * 4 * H) >> 7;
    int nrel, rels[3], node;
    float4 tot;
    const float* bgp = ga.bg;
    if (w < NOP) {
        node = w; nrel = 3; rels[0] = 0; rels[1] = 2; rels[2] = 3;
        float4 b0 = *(const float4*)(bgp + 0 * HID + lane * 4);
        float4 b2 = *(const float4*)(bgp + 2 * HID + lane * 4);
        float4 b3 = *(const float4*)(bgp + 3 * HID + lane * 4);
        tot = make_float4(b0.x + b2.x + b3.x, b0.y + b2.y + b3.y,
                          b0.z + b2.z + b3.z, b0.w + b2.w + b3.w);
    } else if (w < NOP + NMA) {
        return;  // machine rows written by mach_gather
    } else {
        node = w - NOP - NMA; nrel = 1; rels[0] = 4;
        tot = *(const float4*)(bgp + 4 * HID + lane * 4);
    }
    for (int ri = 0; ri < nrel; ri++) {
        int r = rels[ri];
        const int* rp = g_rowptr + r * (NOP + 1);
        int beg = rp[node], end = rp[node + 1];
        const int* sr = g_srcs + r * EMAX;
        const float* aes = g_aes + (size_t)r * EMAX * 8;
        const float* asb = g_asL + (size_t)r * NOP * 8;
        float adv = (lane < H) ? g_adL[(size_t)r * NOP * 8 + (size_t)node * H + lane] : 0.f;
        const float* xs = ga.xs[r];
        int rs = ga.rs[r];
        float m = -1e30f, den = 0.f;
        float4 acc = make_float4(0.f, 0.f, 0.f, 0.f);
        for (int p = beg; p < end; p++) {
            int s = sr[p];
            float lg = 0.f;
            if (lane < H) {
                lg = asb[(size_t)s * H + lane] + adv + aes[(size_t)p * H + lane];
                lg = lg > 0.f ? lg : 0.2f * lg;
            }
            float le = (H == 1) ? __shfl_sync(FULLMASK, lg, 0)
                                : __shfl_sync(FULLMASK, lg, hl);
            if (le > m) {
                float sc = __expf(m - le);
                acc.x *= sc; acc.y *= sc; acc.z *= sc; acc.w *= sc;
                den *= sc;
                m = le;
            }
            float wv = __expf(le - m);
            den += wv;
            const float4 xv = *(const float4*)(xs + (size_t)s * rs + lane * 4);
            acc.x += wv * xv.x; acc.y += wv * xv.y;
            acc.z += wv * xv.z; acc.w += wv * xv.w;
        }
        float inv = 1.f / (den + 1e-16f);
        tot.x += acc.x * inv; tot.y += acc.y * inv;
        tot.z += acc.z * inv; tot.w += acc.w * inv;
    }
    *(float4*)(g_agg + (size_t)w * HID + lane * 4) = tot;
}

// ---------------- machine gather: block per dst node (high degree ~100) ----------------
// Per-lane (m, den) track the head that owns the lane's 4 columns (hl = lane*4*H/128),
// so the cross-warp merge must read head h's stats from a lane with hl == h (lane = 4h
// for H=8; for H=1 all lanes carry head-0 stats and slots 1-7 are never consumed).
template <int H>
__global__ void mach_gather(const float* __restrict__ xs, int rs, const float* __restrict__ bg) {
    int node = blockIdx.x;
    int tid = threadIdx.x, wid = tid >> 5, lane = tid & 31;
    const int* rp = g_rowptr + 1 * (NOP + 1);
    int beg = rp[node], end = rp[node + 1];
    const int* sr = g_srcs + 1 * EMAX;
    const float* aes = g_aes + (size_t)1 * EMAX * 8;
    const float* asb = g_asL + (size_t)1 * NOP * 8;
    float adv = (lane < H) ? g_adL[(size_t)1 * NOP * 8 + (size_t)node * H + lane] : 0.f;
    const int hl = (lane * 4 * H) >> 7;

    float m = -1e30f, den = 0.f;
    float4 acc = make_float4(0.f, 0.f, 0.f, 0.f);
    for (int p = beg + wid; p < end; p += 8) {
        int s = sr[p];
        float lg = 0.f;
        if (lane < H) {
            lg = asb[(size_t)s * H + lane] + adv + aes[(size_t)p * H + lane];
            lg = lg > 0.f ? lg : 0.2f * lg;
        }
        float le = (H == 1) ? __shfl_sync(FULLMASK, lg, 0)
                            : __shfl_sync(FULLMASK, lg, hl);
        if (le > m) {
            float sc = __expf(m - le);
            acc.x *= sc; acc.y *= sc; acc.z *= sc; acc.w *= sc;
            den *= sc;
            m = le;
        }
        float wv = __expf(le - m);
        den += wv;
        const float4 xv = *(const float4*)(xs + (size_t)s * rs + lane * 4);
        acc.x += wv * xv.x; acc.y += wv * xv.y;
        acc.z += wv * xv.z; acc.w += wv * xv.w;
    }
    __shared__ float sm_m[8][8], sm_den[8][8], sm_acc[8][128];
    __shared__ float sm_scale[8][8], sm_inv[8];
    // FIX (round 11 bug): head h's running (m, den) live on lane 4h (whose hl == h),
    // NOT on lane h. Store from the owning lane.
    if ((lane & 3) == 0) {
        int h = lane >> 2;      // = hl of this lane when H==8; head 0 dup when H==1
        sm_m[wid][h] = m;
        sm_den[wid][h] = den;
    }
    *(float4*)&sm_acc[wid][lane * 4] = acc;
    __syncthreads();
    if (tid < 8) {
        int h = tid;
        float mx = -1e30f;
        #pragma unroll
        for (int ww = 0; ww < 8; ww++) mx = fmaxf(mx, sm_m[ww][h]);
        float d = 0.f;
        #pragma unroll
        for (int ww = 0; ww < 8; ww++) {
            float sc = __expf(sm_m[ww][h] - mx);
            sm_scale[ww][h] = sc;
            d += sm_den[ww][h] * sc;
        }
        sm_inv[h] = 1.f / (d + 1e-16f);
    }
    __syncthreads();
    if (tid < 128) {
        int col = tid;
        int h = (col * H) >> 7;
        float a = 0.f;
        #pragma unroll
        for (int ww = 0; ww < 8; ww++) a += sm_acc[ww][col] * sm_scale[ww][h];
        g_agg[(size_t)(NOP + node) * HID + col] = bg[1 * HID + col] + a * sm_inv[h];
    }
}

// ---------------- BN ----------------
__global__ void bn_stats_kernel() {
    const int offs[3] = {0, NOP, NOP + NMA};
    const int cnts[3] = {NOP, NMA, NJOB};
    int type = blockIdx.y;
    int col = threadIdx.x;
    int N = cnts[type], off = offs[type];
    double s = 0.0, s2 = 0.0;
    for (int r = blockIdx.x; r < N; r += 64) {
        float v = g_agg[(size_t)(off + r) * HID + col];
        s += (double)v;
        s2 += (double)v * (double)v;
    }
    g_part[((0 * 3 + type) * 64 + blockIdx.x) * HID + col] = s;
    g_part[((1 * 3 + type) * 64 + blockIdx.x) * HID + col] = s2;
}

__global__ void bn_finalize_kernel(const float* __restrict__ gamma,
                                   const float* __restrict__ beta, int layer) {
    const int cnts[3] = {NOP, NMA, NJOB};
    int idx = threadIdx.x + blockIdx.x * blockDim.x;
    if (idx >= 3 * HID) return;
    int type = idx / HID, col = idx % HID;
    double s = 0.0, s2 = 0.0;
    for (int c = 0; c < 64; c++) {
        s  += g_part[((0 * 3 + type) * 64 + c) * HID + col];
        s2 += g_part[((1 * 3 + type) * 64 + c) * HID + col];
    }
    double N = (double)cnts[type];
    double mu = s / N;
    double var = s2 / N - mu * mu;
    if (var < 0.0) var = 0.0;
    float g = gamma[layer * 3 * HID + type * HID + col];
    float b = beta[layer * 3 * HID + type * HID + col];
    float sc = g * rsqrtf((float)var + 1e-5f);
    g_scale[idx] = sc;
    g_shift[idx] = b - (float)mu * sc;
}

__global__ void bn_apply_kernel(int layer) {
    int idx = blockIdx.x * blockDim.x + threadIdx.x;
    if (idx >= NALL * HID) return;
    int row = idx / HID, col = idx % HID;
    int type = (row < NOP) ? 0 : ((row < NOP + NMA) ? 1 : 2);
    float v = g_agg[idx] * g_scale[type * HID + col] + g_shift[type * HID + col];
    if (layer < NLAYERS - 1) v = fmaxf(v, 0.f);
    float nx = g_x[idx] + v;
    g_x[idx] = nx;
    __nv_bfloat16 hi = __float2bfloat16(nx);
    g_xh[idx] = hi;
    g_xl[idx] = __float2bfloat16(nx - __bfloat162float(hi));
}

// ---------------- launch ----------------
extern "C" void kernel_launch(void* const* d_in, const int* in_sizes, int n_in,
                              void* d_out, int out_size) {
    const float* x_op  = (const float*)d_in[0];
    const float* x_ma  = (const float*)d_in[1];
    const float* x_job = (const float*)d_in[2];

    const int* EI[5];
    const float* EA[5];
    bool interleaved = (in_sizes[4] > 1000000);
    if (interleaved) {
        for (int t = 0; t < 5; t++) {
            EI[t] = (const int*)d_in[3 + 2 * t];
            EA[t] = (const float*)d_in[4 + 2 * t];
        }
    } else {
        for (int t = 0; t < 5; t++) {
            EI[t] = (const int*)d_in[3 + t];
            EA[t] = (const float*)d_in[8 + t];
        }
    }

    const float* Wn_op = (const float*)d_in[13];
    const float* bn_op = (const float*)d_in[14];
    const float* Wn_ma = (const float*)d_in[15];
    const float* bn_ma = (const float*)d_in[16];
    const float* Wn_job = (const float*)d_in[17];
    const float* bn_job = (const float*)d_in[18];
    const float* We_proj = (const float*)d_in[19];
    const float* be_proj = (const float*)d_in[20];
    const float* Wg    = (const float*)d_in[21];
    const float* att_s = (const float*)d_in[22];
    const float* att_d = (const float*)d_in[23];
    const float* Wge   = (const float*)d_in[24];
    const float* att_e = (const float*)d_in[25];
    const float* bg    = (const float*)d_in[26];
    const float* gamma = (const float*)d_in[27];
    const float* beta  = (const float*)d_in[28];
    const float* Wo    = (const float*)d_in[29];
    const float* bo    = (const float*)d_in[30];

    static const int Esz[5]  = {150000, 100000, 150000, 100000, 100000};
    static const int Tdst[5] = {0, 1, 0, 0, 2};
    static const int cntn[3] = {NOP, NMA, NJOB};

    float* gx;    cudaGetSymbolAddress((void**)&gx, g_x);
    float* gxs3;  cudaGetSymbolAddress((void**)&gxs3, g_xs3);
    float* gxsm;  cudaGetSymbolAddress((void**)&gxsm, g_xsm);
    float* gxsj;  cudaGetSymbolAddress((void**)&gxsj, g_xsj);
    float* gasL;  cudaGetSymbolAddress((void**)&gasL, g_asL);
    float* gadL;  cudaGetSymbolAddress((void**)&gadL, g_adL);
    float* gws;   cudaGetSymbolAddress((void**)&gws, g_ws);
    float* gwd;   cudaGetSymbolAddress((void**)&gwd, g_wd);
    float* gMe;   cudaGetSymbolAddress((void**)&gMe, g_Me);
    float* gce;   cudaGetSymbolAddress((void**)&gce, g_ce);
    float* gWcat; cudaGetSymbolAddress((void**)&gWcat, g_Wcat);
    int* grp;     cudaGetSymbolAddress((void**)&grp, g_rowptr);
    int* gsrc;    cudaGetSymbolAddress((void**)&gsrc, g_srcs);
    int* gep;     cudaGetSymbolAddress((void**)&gep, g_epos);
    int* gcnt;    cudaGetSymbolAddress((void**)&gcnt, g_cnt);
    int* gcur;    cudaGetSymbolAddress((void**)&gcur, g_cursor);
    __nv_bfloat16 *gxh, *gxl, *gWcH, *gWcL, *gWmH, *gWmL, *gWjH, *gWjL, *gWoH, *gWoL;
    cudaGetSymbolAddress((void**)&gxh, g_xh);
    cudaGetSymbolAddress((void**)&gxl, g_xl);
    cudaGetSymbolAddress((void**)&gWcH, g_WcatH);
    cudaGetSymbolAddress((void**)&gWcL, g_WcatL);
    cudaGetSymbolAddress((void**)&gWmH, g_WsmH);
    cudaGetSymbolAddress((void**)&gWmL, g_WsmL);
    cudaGetSymbolAddress((void**)&gWjH, g_WsjH);
    cudaGetSymbolAddress((void**)&gWjL, g_WsjL);
    cudaGetSymbolAddress((void**)&gWoH, g_WoH);
    cudaGetSymbolAddress((void**)&gWoL, g_WoL);

    cudaFuncSetAttribute(gemm_tc2, cudaFuncAttributeMaxDynamicSharedMemorySize, TC2_SMEM);

    // ---- launches 0-5: big merged TC GEMM is launch #5 (ncu -s 5 -c 1) ----
    pack_wcat<<<(3 * HID * 384 + 255) / 256, 256>>>(Wg);                                      // 0
    cvt_split<<<(3 * HID * 384 + 255) / 256, 256>>>(gWcat, gWcH, gWcL, 3 * HID * 384);        // 1
    gemm3<<<dim3((NOP + 127) / 128, 1), 256>>>(x_op, Wn_op, bn_op, gx, gxh, gxl, NOP, 64, 128);   // 2
    gemm3<<<dim3((NMA + 127) / 128, 1), 256>>>(x_ma, Wn_ma, bn_ma, gx + (size_t)NOP * HID,
                                               gxh + (size_t)NOP * HID, gxl + (size_t)NOP * HID, NMA, 32, 128);  // 3
    gemm3<<<dim3((NJOB + 127) / 128, 1), 256>>>(x_job, Wn_job, bn_job, gx + (size_t)(NOP + NMA) * HID,
                                                gxh + (size_t)(NOP + NMA) * HID,
                                                gxl + (size_t)(NOP + NMA) * HID, NJOB, 16, 128); // 4
    gemm_tc2<<<dim3((NOP + 63) / 64, 3), 256, TC2_SMEM>>>(gxh, gxl, gWcH, gWcL,
                                                          nullptr, gxs3, NOP, 384);           // 5 <- PROFILED

    // ---- rest of prep ----
    fold_kernel<<<15, 128>>>(Wg, att_s, att_d, Wge, att_e, We_proj, be_proj);
    for (int i = 0; i < NLAYERS; i++) {
        cvt_split<<<(HID * HID + 255) / 256, 256>>>(Wg + (size_t)(i * 5 + 2) * HID * HID,
                                                    gWmH + (size_t)i * HID * HID,
                                                    gWmL + (size_t)i * HID * HID, HID * HID);
        cvt_split<<<(HID * HID + 255) / 256, 256>>>(Wg + (size_t)(i * 5 + 3) * HID * HID,
                                                    gWjH + (size_t)i * HID * HID,
                                                    gWjL + (size_t)i * HID * HID, HID * HID);
    }
    cvt_split<<<(HID * HID + 255) / 256, 256>>>(Wo, gWoH, gWoL, HID * HID);
    for (int t = 0; t < 5; t++) {
        int E = Esz[t];
        int ndst = cntn[Tdst[t]];
        zero_int_kernel<<<(ndst + 255) / 256, 256>>>(gcnt, ndst);
        hist_kernel<<<(E + 255) / 256, 256>>>(EI[t], E, gcnt);
        scan_kernel<<<1, 1024>>>(gcnt, grp + t * (NOP + 1), ndst);
        zero_int_kernel<<<(ndst + 255) / 256, 256>>>(gcur, ndst);
        scatter_kernel<<<(E + 255) / 256, 256>>>(EI[t], E, grp + t * (NOP + 1), gcur,
                                                 gsrc + t * EMAX, gep + t * EMAX);
    }

    EAArgs eaa;
    for (int t = 0; t < 5; t++) eaa.ea[t] = EA[t];

    // ---- layers ----
    for (int i = 0; i < NLAYERS; i++) {
        int H = (i < NLAYERS - 1) ? 8 : 1;
        int b = i * 5;
        if (i > 0)
            gemm_tc2<<<dim3((NOP + 63) / 64, 3), 256, TC2_SMEM>>>(gxh, gxl,
                                                                  gWcH + (size_t)i * HID * 384,
                                                                  gWcL + (size_t)i * HID * 384,
                                                                  nullptr, gxs3, NOP, 384);
        gemm_tc2<<<dim3((NMA + 63) / 64, 1), 256, TC2_SMEM>>>(gxh + (size_t)NOP * HID, gxl + (size_t)NOP * HID,
                                                              gWmH + (size_t)i * HID * HID,
                                                              gWmL + (size_t)i * HID * HID,
                                                              nullptr, gxsm, NMA, 128);
        gemm_tc2<<<dim3((NJOB + 63) / 64, 1), 256, TC2_SMEM>>>(gxh + (size_t)(NOP + NMA) * HID,
                                                               gxl + (size_t)(NOP + NMA) * HID,
                                                               gWjH + (size_t)i * HID * HID,
                                                               gWjL + (size_t)i * HID * HID,
                                                               nullptr, gxsj, NJOB, 128);
        {
            DotArgs da;
            da.w[0] = gws + (b + 0) * 1024; da.out[0] = gasL + (size_t)0 * NOP * 8;
            da.w[1] = gws + (b + 1) * 1024; da.out[1] = gasL + (size_t)1 * NOP * 8;
            da.w[2] = gws + (b + 4) * 1024; da.out[2] = gasL + (size_t)4 * NOP * 8;
            da.w[3] = gwd + (b + 0) * 1024; da.out[3] = gadL + (size_t)0 * NOP * 8;
            da.w[4] = gwd + (b + 2) * 1024; da.out[4] = gadL + (size_t)2 * NOP * 8;
            da.w[5] = gwd + (b + 3) * 1024; da.out[5] = gadL + (size_t)3 * NOP * 8;
            da.nw = 6; da.H = H;
            dots_kernel<<<(NOP + 7) / 8, 256>>>(gx, NOP, da);
        }
        {
            DotArgs da;
            da.w[0] = gws + (b + 2) * 1024; da.out[0] = gasL + (size_t)2 * NOP * 8;
            da.w[1] = gwd + (b + 1) * 1024; da.out[1] = gadL + (size_t)1 * NOP * 8;
            da.nw = 2; da.H = H;
            dots_kernel<<<(NMA + 7) / 8, 256>>>(gx + (size_t)NOP * HID, NMA, da);
        }
        {
            DotArgs da;
            da.w[0] = gws + (b + 3) * 1024; da.out[0] = gasL + (size_t)3 * NOP * 8;
            da.w[1] = gwd + (b + 4) * 1024; da.out[1] = gadL + (size_t)4 * NOP * 8;
            da.nw = 2; da.H = H;
            dots_kernel<<<(NJOB + 7) / 8, 256>>>(gx + (size_t)(NOP + NMA) * HID, NJOB, da);
        }
        edge_ae_all<<<dim3((EMAX + 255) / 256, 5), 256>>>(eaa, gMe + b * 256, gce + b * 8, H);
        {
            GArgs ga;
            ga.xs[0] = gxs3;        ga.rs[0] = 384;
            ga.xs[1] = gxs3 + 128;  ga.rs[1] = 384;
            ga.xs[2] = gxsm;        ga.rs[2] = 128;
            ga.xs[3] = gxsj;        ga.rs[3] = 128;
            ga.xs[4] = gxs3 + 256;  ga.rs[4] = 384;
            ga.bg = bg + i * 5 * HID;
            if (H == 8) {
                gat_gather_all<8><<<(NALL * 32 + 255) / 256, 256>>>(ga);
                mach_gather<8><<<NMA, 256>>>(gxs3 + 128, 384, ga.bg);
            } else {
                gat_gather_all<1><<<(NALL * 32 + 255) / 256, 256>>>(ga);
                mach_gather<1><<<NMA, 256>>>(gxs3 + 128, 384, ga.bg);
            }
        }
        bn_stats_kernel<<<dim3(64, 3), 128>>>();
        bn_finalize_kernel<<<2, 256>>>(gamma, beta, i);
        bn_apply_kernel<<<(NALL * HID + 255) / 256, 256>>>(i);
    }

    // ---- output projection (tensor core) ----
    gemm_tc2<<<dim3((NOP + 63) / 64, 1), 256, TC2_SMEM>>>(gxh, gxl, gWoH, gWoL, bo, (float*)d_out, NOP, 128);
}